// round 5
// baseline (speedup 1.0000x reference)
#include <cuda_runtime.h>
#include <cuda_bf16.h>
#include <math.h>

// Problem dims
#define PB 64      // batch
#define PT 1024    // time
#define PE 256     // embed
#define PU 1024    // units
#define PC3 3072   // 3*U

// Recurrent kernel config
#define NBLK 128       // persistent blocks (1/SM guaranteed by smem)
#define TILE_U 8       // u columns per block: NBLK*TILE_U == PU
#define TPB 256        // threads per block (8 warps)
#define KCH 256        // k-chunk staged in smem
#define NCH (PU / KCH) // 4 chunks
#define HS_STRIDE (KCH + 4)   // 260: mod 32 == 4 -> conflict-free reads; /4 -> f4 aligned

// ---------------------------------------------------------------------------
// scratch: xp[t][b][3U] input projections (written by GEMM1, read by scan)
// ---------------------------------------------------------------------------
__device__ float g_xp[(size_t)PT * PB * PC3];

// grid barrier state
__device__ unsigned g_bar_count = 0;
__device__ unsigned g_bar_gen = 0;

__device__ __forceinline__ void grid_barrier(unsigned nb) {
    __syncthreads();
    if (threadIdx.x == 0) {
        __threadfence();
        unsigned g = *((volatile unsigned*)&g_bar_gen);
        unsigned prev = atomicAdd(&g_bar_count, 1u);
        if (prev == nb - 1u) {
            atomicExch(&g_bar_count, 0u);
            __threadfence();
            atomicAdd(&g_bar_gen, 1u);
        } else {
            while (*((volatile unsigned*)&g_bar_gen) == g) { }
            __threadfence();
        }
    }
    __syncthreads();
}

// ---------------------------------------------------------------------------
// Kernel 1: xp[r][n] = emb[x(b,t)][:] @ W_in[:,n] + b_in[n],  r = t*B + b
// Classic SMEM-tiled SGEMM: BM=128, BN=128, BK=16, 256 threads, 8x8/thread.
// ---------------------------------------------------------------------------
__global__ __launch_bounds__(256) void k_inproj(
    const int* __restrict__ x,
    const float* __restrict__ emb,
    const float* __restrict__ Win,
    const float* __restrict__ bin,
    float* __restrict__ xp)
{
    __shared__ float As[16][132];   // A^T tile, padded
    __shared__ float Bs[16][128];
    __shared__ int rowIdx[128];

    const int tid = threadIdx.x;
    const int m0 = blockIdx.y * 128;
    const int n0 = blockIdx.x * 128;

    if (tid < 128) {
        int m = m0 + tid;                 // m = t*64 + b
        rowIdx[tid] = x[(size_t)(m & 63) * PT + (m >> 6)];
    }
    __syncthreads();

    float acc[8][8];
#pragma unroll
    for (int i = 0; i < 8; i++)
#pragma unroll
        for (int j = 0; j < 8; j++) acc[i][j] = 0.f;

    const int mo = (tid >> 4) * 4;   // 0..60
    const int no = (tid & 15) * 4;   // 0..60

    for (int kt = 0; kt < PE; kt += 16) {
#pragma unroll
        for (int i = 0; i < 2; i++) {
            int fl = tid + i * 256;
            int am = fl >> 2, ac = fl & 3;
            const float4 v = *(const float4*)(emb + (size_t)rowIdx[am] * PE + kt + ac * 4);
            As[ac * 4 + 0][am] = v.x;
            As[ac * 4 + 1][am] = v.y;
            As[ac * 4 + 2][am] = v.z;
            As[ac * 4 + 3][am] = v.w;
        }
#pragma unroll
        for (int i = 0; i < 2; i++) {
            int fl = tid + i * 256;
            int bk = fl >> 5, bn = fl & 31;
            *(float4*)&Bs[bk][bn * 4] =
                *(const float4*)(Win + (size_t)(kt + bk) * PC3 + n0 + bn * 4);
        }
        __syncthreads();

#pragma unroll
        for (int k = 0; k < 16; k++) {
            float a[8], b[8];
            *(float4*)&a[0] = *(const float4*)&As[k][mo];
            *(float4*)&a[4] = *(const float4*)&As[k][mo + 64];
            *(float4*)&b[0] = *(const float4*)&Bs[k][no];
            *(float4*)&b[4] = *(const float4*)&Bs[k][no + 64];
#pragma unroll
            for (int i = 0; i < 8; i++)
#pragma unroll
                for (int j = 0; j < 8; j++)
                    acc[i][j] += a[i] * b[j];
        }
        __syncthreads();
    }

    const float4 bv0 = *(const float4*)(bin + n0 + no);
    const float4 bv1 = *(const float4*)(bin + n0 + no + 64);
#pragma unroll
    for (int i = 0; i < 8; i++) {
        int mrow = m0 + ((i < 4) ? (mo + i) : (mo + 64 + i - 4));
        float4 r0, r1;
        r0.x = acc[i][0] + bv0.x; r0.y = acc[i][1] + bv0.y;
        r0.z = acc[i][2] + bv0.z; r0.w = acc[i][3] + bv0.w;
        r1.x = acc[i][4] + bv1.x; r1.y = acc[i][5] + bv1.y;
        r1.z = acc[i][6] + bv1.z; r1.w = acc[i][7] + bv1.w;
        *(float4*)(xp + (size_t)mrow * PC3 + n0 + no)      = r0;
        *(float4*)(xp + (size_t)mrow * PC3 + n0 + no + 64) = r1;
    }
}

// ---------------------------------------------------------------------------
// fast activations (tolerance is 1e-3; fp32 path measured 2.5e-7)
// ---------------------------------------------------------------------------
__device__ __forceinline__ float sig_fast(float v) {
    return 1.0f / (1.0f + __expf(-v));
}
__device__ __forceinline__ float tanh_fast(float v) {
    float ax = fabsf(v);
    float e  = __expf(2.0f * ax);          // inf for large ax -> t = 1
    float t  = 1.0f - 2.0f / (e + 1.0f);
    return copysignf(t, v);
}

// ---------------------------------------------------------------------------
// Kernel 2: persistent GRU scan with packed f32x2 FMA.
// 128 blocks x 256 threads; block p owns u in [p*8, p*8+8).
// Warp w owns b in [8w, 8w+8); lane = bl*4 + kg: bl = local b, kg = k-split.
// Each lane accumulates 12 f32x2 pairs: (g, u-pair) for its b over its
// k-stripe (kk = kg + 4i). One h load feeds 12 FFMA2. W (no duplication,
// pairs contiguous along u) = 96KB smem; h staged per 256-k chunk (66.5KB).
// End of step: 2-round shfl_xor reduce over kg, leaders (kg==0) do gates.
// ---------------------------------------------------------------------------
__global__ __launch_bounds__(TPB, 1) void k_gru(
    const float* __restrict__ xp,
    const float* __restrict__ h0,
    const float* __restrict__ Wrec,
    const float* __restrict__ brec,
    float* __restrict__ out,
    float* __restrict__ hlast)
{
    extern __shared__ float sm[];
    float* Ws  = sm;                         // [1024][24]  (k, g*8+u_local)
    float* hs  = Ws + 1024 * 24;             // [64][HS_STRIDE]
    float* brs = hs + 64 * HS_STRIDE;        // [24]

    const int tid  = threadIdx.x;
    const int warp = tid >> 5;
    const int lane = tid & 31;
    const int bl   = lane >> 2;              // 0..7
    const int kg   = lane & 3;               // 0..3
    const int ubase = blockIdx.x * TILE_U;
    const int b     = warp * 8 + bl;
    const bool lead = (kg == 0);

    // cache W_rec block-column in SMEM: Ws[k*24 + g*8 + ul]
    for (int idx = tid; idx < 1024 * 24; idx += TPB) {
        int k = idx / 24, r = idx - k * 24;
        int g = r >> 3, ul = r & 7;
        Ws[idx] = Wrec[(size_t)k * PC3 + g * PU + ubase + ul];
    }
    if (tid < 24) brs[tid] = brec[(tid >> 3) * PU + ubase + (tid & 7)];

    for (int t = 0; t < PT; t++) {
        // ---- prefetch epilogue operands (latency hidden under GEMM) ----
        float xzv[8], xrv[8], xhv[8], hpv[8];
        if (lead) {
            const float* xrow = xp + ((size_t)t * PB + b) * PC3 + ubase;
            *(float4*)&xzv[0] = *(const float4*)(xrow);
            *(float4*)&xzv[4] = *(const float4*)(xrow + 4);
            *(float4*)&xrv[0] = *(const float4*)(xrow + PU);
            *(float4*)&xrv[4] = *(const float4*)(xrow + PU + 4);
            *(float4*)&xhv[0] = *(const float4*)(xrow + 2 * PU);
            *(float4*)&xhv[4] = *(const float4*)(xrow + 2 * PU + 4);
            const float* hr = (t == 0)
                ? (h0 + (size_t)b * PU + ubase)
                : (out + ((size_t)b * PT + (t - 1)) * PU + ubase);
            *(float4*)&hpv[0] = *(const float4*)(hr);
            *(float4*)&hpv[4] = *(const float4*)(hr + 4);
        }

        unsigned long long acc[12];
#pragma unroll
        for (int j = 0; j < 12; j++) acc[j] = 0ull;

#pragma unroll 1
        for (int ch = 0; ch < NCH; ch++) {
            const int kc = ch * KCH;
            __syncthreads();
            // stage h_{t-1}[b][kc..kc+KCH) -> hs[b][kk] (f4 both sides)
#pragma unroll
            for (int i = 0; i < (PB * KCH / 4) / TPB; i++) {   // 16
                int fl = tid + i * TPB;
                int bs = fl >> 6;         // 0..63
                int kq = fl & 63;         // float4 index
                float4 v;
                if (t == 0)
                    v = *(const float4*)(h0 + (size_t)bs * PU + kc + kq * 4);
                else
                    v = *(const float4*)(out + ((size_t)bs * PT + (t - 1)) * PU + kc + kq * 4);
                *(float4*)(hs + bs * HS_STRIDE + kq * 4) = v;
            }
            __syncthreads();

            const float* hrow  = hs + b * HS_STRIDE + kg;
            const float* wbase = Ws + (kc + kg) * 24;
#pragma unroll 4
            for (int i = 0; i < KCH / 4; i++) {
                float h = hrow[4 * i];
                unsigned long long hh;
                asm("mov.b64 %0, {%1, %1};" : "=l"(hh) : "r"(__float_as_uint(h)));
                const ulonglong2* wp = (const ulonglong2*)(wbase + 4 * i * 24);
                ulonglong2 w0 = wp[0], w1 = wp[1], w2 = wp[2];
                ulonglong2 w3 = wp[3], w4 = wp[4], w5 = wp[5];
                asm("fma.rn.f32x2 %0, %1, %2, %0;" : "+l"(acc[0])  : "l"(hh), "l"(w0.x));
                asm("fma.rn.f32x2 %0, %1, %2, %0;" : "+l"(acc[1])  : "l"(hh), "l"(w0.y));
                asm("fma.rn.f32x2 %0, %1, %2, %0;" : "+l"(acc[2])  : "l"(hh), "l"(w1.x));
                asm("fma.rn.f32x2 %0, %1, %2, %0;" : "+l"(acc[3])  : "l"(hh), "l"(w1.y));
                asm("fma.rn.f32x2 %0, %1, %2, %0;" : "+l"(acc[4])  : "l"(hh), "l"(w2.x));
                asm("fma.rn.f32x2 %0, %1, %2, %0;" : "+l"(acc[5])  : "l"(hh), "l"(w2.y));
                asm("fma.rn.f32x2 %0, %1, %2, %0;" : "+l"(acc[6])  : "l"(hh), "l"(w3.x));
                asm("fma.rn.f32x2 %0, %1, %2, %0;" : "+l"(acc[7])  : "l"(hh), "l"(w3.y));
                asm("fma.rn.f32x2 %0, %1, %2, %0;" : "+l"(acc[8])  : "l"(hh), "l"(w4.x));
                asm("fma.rn.f32x2 %0, %1, %2, %0;" : "+l"(acc[9])  : "l"(hh), "l"(w4.y));
                asm("fma.rn.f32x2 %0, %1, %2, %0;" : "+l"(acc[10]) : "l"(hh), "l"(w5.x));
                asm("fma.rn.f32x2 %0, %1, %2, %0;" : "+l"(acc[11]) : "l"(hh), "l"(w5.y));
            }
        }

        // ---- reduce across the 4 k-split lanes (kg bits = lane bits 0..1) ----
        float a[24];
#pragma unroll
        for (int j = 0; j < 12; j++) {
            a[2 * j]     = __uint_as_float((unsigned)(acc[j] & 0xffffffffull));
            a[2 * j + 1] = __uint_as_float((unsigned)(acc[j] >> 32));
        }
#pragma unroll
        for (int d = 1; d <= 2; d <<= 1) {
#pragma unroll
            for (int j = 0; j < 24; j++)
                a[j] += __shfl_xor_sync(0xffffffffu, a[j], d);
        }

        // ---- gate epilogue on leaders ----
        if (lead) {
            float hn[8];
#pragma unroll
            for (int ul = 0; ul < 8; ul++) {
                int up = ul >> 1, half = ul & 1;
                float az = a[2 * (0 * 4 + up) + half];
                float ar = a[2 * (1 * 4 + up) + half];
                float ah = a[2 * (2 * 4 + up) + half];
                float z = sig_fast(xzv[ul] + az + brs[ul]);
                float r = sig_fast(xrv[ul] + ar + brs[8 + ul]);
                float c = tanh_fast(xhv[ul] + r * (ah + brs[16 + ul]));
                hn[ul] = z * hpv[ul] + (1.f - z) * c;
            }
            float* orow = out + ((size_t)b * PT + t) * PU + ubase;
            *(float4*)(orow)     = *(float4*)&hn[0];
            *(float4*)(orow + 4) = *(float4*)&hn[4];
            if (t == PT - 1 && hlast != nullptr) {
                float* hl = hlast + (size_t)b * PU + ubase;
                *(float4*)(hl)     = *(float4*)&hn[0];
                *(float4*)(hl + 4) = *(float4*)&hn[4];
            }
        }

        grid_barrier(NBLK);
    }
}

// ---------------------------------------------------------------------------
// launch
// ---------------------------------------------------------------------------
extern "C" void kernel_launch(void* const* d_in, const int* in_sizes, int n_in,
                              void* d_out, int out_size)
{
    const int*   x       = (const int*)  d_in[0];
    const float* initial = (const float*)d_in[1];
    const float* emb     = (const float*)d_in[2];
    const float* Win     = (const float*)d_in[3];
    const float* Wrec    = (const float*)d_in[4];
    const float* bin     = (const float*)d_in[5];
    const float* brec    = (const float*)d_in[6];

    float* out = (float*)d_out;
    float* hlast = nullptr;
    const long long n_outputs = (long long)PB * PT * PU;
    if ((long long)out_size >= n_outputs + (long long)PB * PU) {
        hlast = out + (size_t)n_outputs;
    }

    float* xp = nullptr;
    cudaGetSymbolAddress((void**)&xp, g_xp);

    // GEMM1: embedding gather + input projection
    dim3 g1(PC3 / 128, (PT * PB) / 128);
    k_inproj<<<g1, 256>>>(x, emb, Win, bin, xp);

    // GRU scan (persistent, grid barrier per step)
    const int smem = (1024 * 24 + 64 * HS_STRIDE + 24 + 8) * (int)sizeof(float);
    cudaFuncSetAttribute(k_gru, cudaFuncAttributeMaxDynamicSharedMemorySize, smem);
    k_gru<<<NBLK, TPB, smem>>>(xp, initial, Wrec, brec, out, hlast);
}

// round 6
// speedup vs baseline: 2.4415x; 2.4415x over previous
#include <cuda_runtime.h>
#include <cuda_bf16.h>
#include <math.h>

// Problem dims
#define PB 64      // batch
#define PT 1024    // time
#define PE 256     // embed
#define PU 1024    // units
#define PC3 3072   // 3*U

// Recurrent kernel config
#define NBLK 128       // persistent blocks (1/SM)
#define TILE_U 8       // u columns per block
#define TPB 512        // 16 warps
#define NSL 4          // k-slices (warp dim)
#define KSL (PU / NSL) // 256 k per slice
#define KCH 64         // k staged per slice per stage-iter
#define NCHUNK (KSL / KCH) // 4
#define HST 68         // hs row stride (floats), 17 float4s

// ---------------------------------------------------------------------------
// scratch
// ---------------------------------------------------------------------------
__device__ float g_xp[(size_t)PT * PB * PC3];
__device__ float g_hTA[PU * PB];   // h transposed [k][b], double buffered
__device__ float g_hTB[PU * PB];

// grid barrier state
__device__ unsigned g_bar_count = 0;
__device__ unsigned g_bar_gen = 0;

__device__ __forceinline__ void grid_barrier(unsigned nb) {
    __syncthreads();
    if (threadIdx.x == 0) {
        __threadfence();
        unsigned g = *((volatile unsigned*)&g_bar_gen);
        unsigned prev = atomicAdd(&g_bar_count, 1u);
        if (prev == nb - 1u) {
            atomicExch(&g_bar_count, 0u);
            __threadfence();
            atomicAdd(&g_bar_gen, 1u);
        } else {
            while (*((volatile unsigned*)&g_bar_gen) == g) { }
            __threadfence();
        }
    }
    __syncthreads();
}

// ---------------------------------------------------------------------------
// Kernel 0: transpose initial state into hTA: hT[k][b] = initial[b][k]
// ---------------------------------------------------------------------------
__global__ void k_hT_init(const float* __restrict__ h0, float* __restrict__ hT) {
    int idx = blockIdx.x * blockDim.x + threadIdx.x;   // over PU*PB
    if (idx < PU * PB) {
        int k = idx >> 6, b = idx & 63;
        hT[idx] = h0[(size_t)b * PU + k];
    }
}

// ---------------------------------------------------------------------------
// Kernel 1: xp[r][n] = emb[x(b,t)][:] @ W_in[:,n] + b_in[n],  r = t*B + b
// ---------------------------------------------------------------------------
__global__ __launch_bounds__(256) void k_inproj(
    const int* __restrict__ x,
    const float* __restrict__ emb,
    const float* __restrict__ Win,
    const float* __restrict__ bin,
    float* __restrict__ xp)
{
    __shared__ float As[16][132];
    __shared__ float Bs[16][128];
    __shared__ int rowIdx[128];

    const int tid = threadIdx.x;
    const int m0 = blockIdx.y * 128;
    const int n0 = blockIdx.x * 128;

    if (tid < 128) {
        int m = m0 + tid;                 // m = t*64 + b
        rowIdx[tid] = x[(size_t)(m & 63) * PT + (m >> 6)];
    }
    __syncthreads();

    float acc[8][8];
#pragma unroll
    for (int i = 0; i < 8; i++)
#pragma unroll
        for (int j = 0; j < 8; j++) acc[i][j] = 0.f;

    const int mo = (tid >> 4) * 4;
    const int no = (tid & 15) * 4;

    for (int kt = 0; kt < PE; kt += 16) {
#pragma unroll
        for (int i = 0; i < 2; i++) {
            int fl = tid + i * 256;
            int am = fl >> 2, ac = fl & 3;
            const float4 v = *(const float4*)(emb + (size_t)rowIdx[am] * PE + kt + ac * 4);
            As[ac * 4 + 0][am] = v.x;
            As[ac * 4 + 1][am] = v.y;
            As[ac * 4 + 2][am] = v.z;
            As[ac * 4 + 3][am] = v.w;
        }
#pragma unroll
        for (int i = 0; i < 2; i++) {
            int fl = tid + i * 256;
            int bk = fl >> 5, bn = fl & 31;
            *(float4*)&Bs[bk][bn * 4] =
                *(const float4*)(Win + (size_t)(kt + bk) * PC3 + n0 + bn * 4);
        }
        __syncthreads();

#pragma unroll
        for (int k = 0; k < 16; k++) {
            float a[8], b[8];
            *(float4*)&a[0] = *(const float4*)&As[k][mo];
            *(float4*)&a[4] = *(const float4*)&As[k][mo + 64];
            *(float4*)&b[0] = *(const float4*)&Bs[k][no];
            *(float4*)&b[4] = *(const float4*)&Bs[k][no + 64];
#pragma unroll
            for (int i = 0; i < 8; i++)
#pragma unroll
                for (int j = 0; j < 8; j++)
                    acc[i][j] += a[i] * b[j];
        }
        __syncthreads();
    }

    const float4 bv0 = *(const float4*)(bin + n0 + no);
    const float4 bv1 = *(const float4*)(bin + n0 + no + 64);
#pragma unroll
    for (int i = 0; i < 8; i++) {
        int mrow = m0 + ((i < 4) ? (mo + i) : (mo + 64 + i - 4));
        float4 r0, r1;
        r0.x = acc[i][0] + bv0.x; r0.y = acc[i][1] + bv0.y;
        r0.z = acc[i][2] + bv0.z; r0.w = acc[i][3] + bv0.w;
        r1.x = acc[i][4] + bv1.x; r1.y = acc[i][5] + bv1.y;
        r1.z = acc[i][6] + bv1.z; r1.w = acc[i][7] + bv1.w;
        *(float4*)(xp + (size_t)mrow * PC3 + n0 + no)      = r0;
        *(float4*)(xp + (size_t)mrow * PC3 + n0 + no + 64) = r1;
    }
}

// ---------------------------------------------------------------------------
// fast activations (tolerance 1e-3; measured path ~2.5e-6)
// ---------------------------------------------------------------------------
__device__ __forceinline__ float sig_fast(float v) {
    return 1.0f / (1.0f + __expf(-v));
}
__device__ __forceinline__ float tanh_fast(float v) {
    float ax = fabsf(v);
    float e  = __expf(2.0f * ax);
    float t  = 1.0f - 2.0f / (e + 1.0f);
    return copysignf(t, v);
}

// ---------------------------------------------------------------------------
// Kernel 2: persistent GRU scan.
// Block owns 8 u. 16 warps: warp = s*4 + bh*2 + q
//   s  = k-slice (0..3), 256 k each
//   bh = batch half (lane -> b = bh*32 + lane)
//   q  = u-quad (u = ubase + q*4 + 0..3)
// Lane accumulates 6 f32x2 (3 gates x 2 u-pairs) for its (b, 4u) over its
// k-slice. h read once per kk (LDS.32, 1 wf), dup'd via mov.b64; W read as
// 3 broadcast LDS.128 (z,r,h gate quads). k-slices reduced via smem, gate
// epilogue on s==0 warps, coalesced output + transposed hT for next step.
// ---------------------------------------------------------------------------
__global__ __launch_bounds__(TPB, 1) void k_gru(
    const float* __restrict__ xp,
    const float* __restrict__ h0,
    const float* __restrict__ Wrec,
    const float* __restrict__ brec,
    float* __restrict__ out,
    float* __restrict__ hlast)
{
    extern __shared__ float sm[];
    float* Ws  = sm;                          // [1024][3][8]  = 98304 B
    float* hs  = Ws + 1024 * 24;              // [4][KCH][HST] = 69632 B (reused as red)
    float* os  = hs + NSL * KCH * HST;        // [64][8]       = 2048 B
    float* brs = os + 64 * 8;                 // [24]

    const int tid  = threadIdx.x;
    const int warp = tid >> 5;
    const int lane = tid & 31;
    const int s    = warp >> 2;
    const int bh   = (warp >> 1) & 1;
    const int q    = warp & 1;
    const int b    = bh * 32 + lane;
    const int ubase = blockIdx.x * TILE_U;

    float* hTA = g_hTA;
    float* hTB = g_hTB;

    // cache W_rec block-column: Ws[k*24 + g*8 + u]
    for (int idx = tid; idx < 1024 * 24; idx += TPB) {
        int k = idx / 24, r = idx - k * 24;
        int g = r >> 3, ul = r & 7;
        Ws[idx] = Wrec[(size_t)k * PC3 + g * PU + ubase + ul];
    }
    if (tid < 24) brs[tid] = brec[(tid >> 3) * PU + ubase + (tid & 7)];

    const ulonglong2* Wsu = (const ulonglong2*)Ws;

    for (int t = 0; t < PT; t++) {
        const float* hTr = (t & 1) ? hTB : hTA;
        float*       hTw = (t & 1) ? hTA : hTB;

        // ---- prefetch epilogue operands (s==0 warps) ----
        float4 xz, xr, xh, hp;
        if (s == 0) {
            const float* xrow = xp + ((size_t)t * PB + b) * PC3 + ubase + q * 4;
            xz = *(const float4*)(xrow);
            xr = *(const float4*)(xrow + PU);
            xh = *(const float4*)(xrow + 2 * PU);
            const float* hr = (t == 0)
                ? (h0 + (size_t)b * PU + ubase + q * 4)
                : (out + ((size_t)b * PT + (t - 1)) * PU + ubase + q * 4);
            hp = *(const float4*)(hr);
        }

        unsigned long long acc[6];   // [g][upair]
#pragma unroll
        for (int j = 0; j < 6; j++) acc[j] = 0ull;

#pragma unroll 1
        for (int c = 0; c < NCHUNK; c++) {
            __syncthreads();
            // stage KCH k's per slice from hT (pure f4 copy, coalesced)
#pragma unroll
            for (int i = 0; i < (NSL * KCH * PB / 4) / TPB; i++) {   // 8
                int fl = tid + i * TPB;
                int s2 = fl >> 10;
                int rem = fl & 1023;
                int kk = rem >> 4;
                int bq = rem & 15;
                int gk = s2 * KSL + c * KCH + kk;
                float4 v = *(const float4*)(hTr + (size_t)gk * PB + bq * 4);
                *(float4*)(hs + (s2 * KCH + kk) * HST + bq * 4) = v;
            }
            __syncthreads();

            const float* hb = hs + (s * KCH) * HST + b;
            const ulonglong2* wb = Wsu + (size_t)(s * KSL + c * KCH) * 6 + q;
#pragma unroll 4
            for (int kk = 0; kk < KCH; kk++) {
                float hv = hb[kk * HST];
                unsigned long long hh;
                asm("mov.b64 %0, {%1, %1};" : "=l"(hh) : "r"(__float_as_uint(hv)));
                ulonglong2 wz = wb[kk * 6 + 0];
                ulonglong2 wr = wb[kk * 6 + 2];
                ulonglong2 wh = wb[kk * 6 + 4];
                asm("fma.rn.f32x2 %0, %1, %2, %0;" : "+l"(acc[0]) : "l"(hh), "l"(wz.x));
                asm("fma.rn.f32x2 %0, %1, %2, %0;" : "+l"(acc[1]) : "l"(hh), "l"(wz.y));
                asm("fma.rn.f32x2 %0, %1, %2, %0;" : "+l"(acc[2]) : "l"(hh), "l"(wr.x));
                asm("fma.rn.f32x2 %0, %1, %2, %0;" : "+l"(acc[3]) : "l"(hh), "l"(wr.y));
                asm("fma.rn.f32x2 %0, %1, %2, %0;" : "+l"(acc[4]) : "l"(hh), "l"(wh.x));
                asm("fma.rn.f32x2 %0, %1, %2, %0;" : "+l"(acc[5]) : "l"(hh), "l"(wh.y));
            }
        }

        // ---- reduce the 4 k-slices through smem (deterministic order) ----
        __syncthreads();
        float2* red = (float2*)hs;
#pragma unroll
        for (int j = 0; j < 6; j++) {
            float lo, hi;
            asm("mov.b64 {%0, %1}, %2;" : "=r"(*(unsigned*)&lo), "=r"(*(unsigned*)&hi) : "l"(acc[j]));
            red[((warp << 5) + lane) * 6 + j] = make_float2(lo, hi);
        }
        __syncthreads();

        if (s == 0) {
            float a[12];
#pragma unroll
            for (int j = 0; j < 6; j++) {
                float2 v = red[((warp << 5) + lane) * 6 + j];
                a[2 * j] = v.x; a[2 * j + 1] = v.y;
            }
#pragma unroll
            for (int ss = 1; ss < NSL; ss++) {
                int w2 = (ss << 2) + (bh << 1) + q;
#pragma unroll
                for (int j = 0; j < 6; j++) {
                    float2 v = red[((w2 << 5) + lane) * 6 + j];
                    a[2 * j] += v.x; a[2 * j + 1] += v.y;
                }
            }

            // gate epilogue: 4 u for this b
            float xzv[4] = {xz.x, xz.y, xz.z, xz.w};
            float xrv[4] = {xr.x, xr.y, xr.z, xr.w};
            float xhv[4] = {xh.x, xh.y, xh.z, xh.w};
            float hpv[4] = {hp.x, hp.y, hp.z, hp.w};
            float hn[4];
#pragma unroll
            for (int ul = 0; ul < 4; ul++) {
                int up = ul >> 1, half = ul & 1;
                int uloc = q * 4 + ul;
                float az = a[(0 * 2 + up) * 2 + half];
                float ar = a[(1 * 2 + up) * 2 + half];
                float ah = a[(2 * 2 + up) * 2 + half];
                float z = sig_fast(xzv[ul] + az + brs[uloc]);
                float r = sig_fast(xrv[ul] + ar + brs[8 + uloc]);
                float cd = tanh_fast(xhv[ul] + r * (ah + brs[16 + uloc]));
                hn[ul] = z * hpv[ul] + (1.f - z) * cd;
            }
            *(float4*)(os + b * 8 + q * 4) = *(float4*)hn;
        }
        __syncthreads();

        // coalesced outputs: out[b][t][uslice], hT[k=u][b]
        if (tid < 128) {
            int bb = tid >> 1, half = tid & 1;
            float4 v = *(const float4*)(os + bb * 8 + half * 4);
            *(float4*)(out + ((size_t)bb * PT + t) * PU + ubase + half * 4) = v;
            if (t == PT - 1 && hlast != nullptr) {
                *(float4*)(hlast + (size_t)bb * PU + ubase + half * 4) = v;
            }
        }
        {
            int uu = tid >> 6, bb = tid & 63;
            hTw[(size_t)(ubase + uu) * PB + bb] = os[bb * 8 + uu];
        }

        grid_barrier(NBLK);
    }
}

// ---------------------------------------------------------------------------
// launch
// ---------------------------------------------------------------------------
extern "C" void kernel_launch(void* const* d_in, const int* in_sizes, int n_in,
                              void* d_out, int out_size)
{
    const int*   x       = (const int*)  d_in[0];
    const float* initial = (const float*)d_in[1];
    const float* emb     = (const float*)d_in[2];
    const float* Win     = (const float*)d_in[3];
    const float* Wrec    = (const float*)d_in[4];
    const float* bin     = (const float*)d_in[5];
    const float* brec    = (const float*)d_in[6];

    float* out = (float*)d_out;
    float* hlast = nullptr;
    const long long n_outputs = (long long)PB * PT * PU;
    if ((long long)out_size >= n_outputs + (long long)PB * PU) {
        hlast = out + (size_t)n_outputs;
    }

    float* xp = nullptr;
    cudaGetSymbolAddress((void**)&xp, g_xp);
    float* hTA = nullptr;
    cudaGetSymbolAddress((void**)&hTA, g_hTA);

    // h0 transpose for step 0 staging
    k_hT_init<<<(PU * PB + 255) / 256, 256>>>(initial, hTA);

    // GEMM1: embedding gather + input projection
    dim3 g1(PC3 / 128, (PT * PB) / 128);
    k_inproj<<<g1, 256>>>(x, emb, Win, bin, xp);

    // GRU scan
    const int smem = (1024 * 24 + NSL * KCH * HST + 64 * 8 + 24 + 8) * (int)sizeof(float);
    cudaFuncSetAttribute(k_gru, cudaFuncAttributeMaxDynamicSharedMemorySize, smem);
    k_gru<<<NBLK, TPB, smem>>>(xp, initial, Wrec, brec, out, hlast);
}

// round 8
// speedup vs baseline: 4.6925x; 1.9220x over previous
#include <cuda_runtime.h>
#include <cuda_bf16.h>
#include <math.h>
#include <stdint.h>

// Problem dims
#define PB 64
#define PT 1024
#define PE 256
#define PU 1024
#define PC3 3072

#define NBLK 128
#define TILE_U 8          // u per block; N = 24 cols (3 gates x 8 u)
#define TPB 256           // 8 warps
#define NCOL 24
#define KCHUNK 256        // k per staged A chunk
#define NCHNK (PU / KCHUNK)
#define AROWB 528         // A smem row stride in bytes (33 x 16B, conflict-free ldmatrix)
#define ABUFB (128 * AROWB)   // 67584 B per buffer
#define WLOST 1032        // Wlo smem row stride (bf16 elems) = 2064 B (129 x 16B)

// smem byte offsets
#define SM_A     0                       // 2 buffers = 135168
#define SM_WLO   (2 * ABUFB)             // 49536 -> ends 184704
#define SM_OS    184704                  // float os[64][8]      = 2048
#define SM_OSH   186752                  // u32 osh[64][4]       = 1024
#define SM_OSL   187776                  // u32 osl[64][4]       = 1024
#define SM_BRS   188800                  // float brs[24]        = 96
#define SM_TOTAL 188928
// Dp overlays the A buffers after MMAs complete: float Dp[8][128][24] = 98304 B

// ---------------------------------------------------------------------------
// global scratch
// ---------------------------------------------------------------------------
__device__ float g_xp[(size_t)PT * PB * PC3];
__device__ __nv_bfloat16 g_hhi[2][PB * PU];
__device__ __nv_bfloat16 g_hlo[2][PB * PU];

__device__ unsigned g_bar_count = 0;
__device__ unsigned g_bar_gen = 0;

__device__ __forceinline__ void grid_barrier(unsigned nb) {
    __syncthreads();
    if (threadIdx.x == 0) {
        __threadfence();
        unsigned g = *((volatile unsigned*)&g_bar_gen);
        unsigned prev = atomicAdd(&g_bar_count, 1u);
        if (prev == nb - 1u) {
            atomicExch(&g_bar_count, 0u);
            __threadfence();
            atomicAdd(&g_bar_gen, 1u);
        } else {
            while (*((volatile unsigned*)&g_bar_gen) == g) { }
            __threadfence();
        }
    }
    __syncthreads();
}

// ---------------------------------------------------------------------------
// mma / ldmatrix wrappers (baseline PTX, valid on compute_103)
// ---------------------------------------------------------------------------
__device__ __forceinline__ uint32_t smem_u32(const void* p) {
    uint32_t a;
    asm("{ .reg .u64 t; cvta.to.shared.u64 t, %1; cvt.u32.u64 %0, t; }" : "=r"(a) : "l"(p));
    return a;
}
__device__ __forceinline__ void mma_bf16(float* d, const uint32_t* a, const uint32_t* b) {
    asm volatile(
        "mma.sync.aligned.m16n8k16.row.col.f32.bf16.bf16.f32 "
        "{%0,%1,%2,%3}, {%4,%5,%6,%7}, {%8,%9}, {%0,%1,%2,%3};"
        : "+f"(d[0]), "+f"(d[1]), "+f"(d[2]), "+f"(d[3])
        : "r"(a[0]), "r"(a[1]), "r"(a[2]), "r"(a[3]), "r"(b[0]), "r"(b[1]));
}
__device__ __forceinline__ void ldsm_x4(uint32_t* r, uint32_t addr) {
    asm volatile("ldmatrix.sync.aligned.m8n8.x4.shared.b16 {%0,%1,%2,%3}, [%4];"
                 : "=r"(r[0]), "=r"(r[1]), "=r"(r[2]), "=r"(r[3]) : "r"(addr));
}
__device__ __forceinline__ uint32_t pack_bf16x2(float lo, float hi) {
    __nv_bfloat162 v = __floats2bfloat162_rn(lo, hi);
    return *(uint32_t*)&v;
}

__device__ __forceinline__ float sig_fast(float v) {
    return 1.0f / (1.0f + __expf(-v));
}
__device__ __forceinline__ float tanh_fast(float v) {
    float ax = fabsf(v);
    float e  = __expf(2.0f * ax);
    float t  = 1.0f - 2.0f / (e + 1.0f);
    return copysignf(t, v);
}

// ---------------------------------------------------------------------------
// Kernel 0: split initial state into bf16 hi/lo (parity-0 buffers)
// ---------------------------------------------------------------------------
__global__ void k_split_init(const float* __restrict__ h0,
                             __nv_bfloat16* __restrict__ hi,
                             __nv_bfloat16* __restrict__ lo) {
    int idx = blockIdx.x * blockDim.x + threadIdx.x;
    if (idx < PB * PU) {
        float v = h0[idx];
        __nv_bfloat16 h = __float2bfloat16_rn(v);
        hi[idx] = h;
        lo[idx] = __float2bfloat16_rn(v - __bfloat162float(h));
    }
}

// ---------------------------------------------------------------------------
// Kernel 1: xp = emb[x] @ W_in + b_in  (fp32 SGEMM, unchanged)
// ---------------------------------------------------------------------------
__global__ __launch_bounds__(256) void k_inproj(
    const int* __restrict__ x,
    const float* __restrict__ emb,
    const float* __restrict__ Win,
    const float* __restrict__ bin,
    float* __restrict__ xp)
{
    __shared__ float As[16][132];
    __shared__ float Bs[16][128];
    __shared__ int rowIdx[128];

    const int tid = threadIdx.x;
    const int m0 = blockIdx.y * 128;
    const int n0 = blockIdx.x * 128;

    if (tid < 128) {
        int m = m0 + tid;
        rowIdx[tid] = x[(size_t)(m & 63) * PT + (m >> 6)];
    }
    __syncthreads();

    float acc[8][8];
#pragma unroll
    for (int i = 0; i < 8; i++)
#pragma unroll
        for (int j = 0; j < 8; j++) acc[i][j] = 0.f;

    const int mo = (tid >> 4) * 4;
    const int no = (tid & 15) * 4;

    for (int kt = 0; kt < PE; kt += 16) {
#pragma unroll
        for (int i = 0; i < 2; i++) {
            int fl = tid + i * 256;
            int am = fl >> 2, ac = fl & 3;
            const float4 v = *(const float4*)(emb + (size_t)rowIdx[am] * PE + kt + ac * 4);
            As[ac * 4 + 0][am] = v.x;
            As[ac * 4 + 1][am] = v.y;
            As[ac * 4 + 2][am] = v.z;
            As[ac * 4 + 3][am] = v.w;
        }
#pragma unroll
        for (int i = 0; i < 2; i++) {
            int fl = tid + i * 256;
            int bk = fl >> 5, bn = fl & 31;
            *(float4*)&Bs[bk][bn * 4] =
                *(const float4*)(Win + (size_t)(kt + bk) * PC3 + n0 + bn * 4);
        }
        __syncthreads();

#pragma unroll
        for (int k = 0; k < 16; k++) {
            float a[8], b[8];
            *(float4*)&a[0] = *(const float4*)&As[k][mo];
            *(float4*)&a[4] = *(const float4*)&As[k][mo + 64];
            *(float4*)&b[0] = *(const float4*)&Bs[k][no];
            *(float4*)&b[4] = *(const float4*)&Bs[k][no + 64];
#pragma unroll
            for (int i = 0; i < 8; i++)
#pragma unroll
                for (int j = 0; j < 8; j++)
                    acc[i][j] += a[i] * b[j];
        }
        __syncthreads();
    }

    const float4 bv0 = *(const float4*)(bin + n0 + no);
    const float4 bv1 = *(const float4*)(bin + n0 + no + 64);
#pragma unroll
    for (int i = 0; i < 8; i++) {
        int mrow = m0 + ((i < 4) ? (mo + i) : (mo + 64 + i - 4));
        float4 r0, r1;
        r0.x = acc[i][0] + bv0.x; r0.y = acc[i][1] + bv0.y;
        r0.z = acc[i][2] + bv0.z; r0.w = acc[i][3] + bv0.w;
        r1.x = acc[i][4] + bv1.x; r1.y = acc[i][5] + bv1.y;
        r1.z = acc[i][6] + bv1.z; r1.w = acc[i][7] + bv1.w;
        *(float4*)(xp + (size_t)mrow * PC3 + n0 + no)      = r0;
        *(float4*)(xp + (size_t)mrow * PC3 + n0 + no + 64) = r1;
    }
}

// ---------------------------------------------------------------------------
// stage one 256-k chunk of A = [h_hi(64 rows); h_lo(64 rows)] into smem
// ---------------------------------------------------------------------------
__device__ __forceinline__ void stage_chunk(char* Abuf,
                                            const __nv_bfloat16* __restrict__ sHi,
                                            const __nv_bfloat16* __restrict__ sLo,
                                            int kc, int tid)
{
#pragma unroll
    for (int i = 0; i < 16; i++) {
        int fl = tid + i * TPB;          // 0..4095
        int m  = fl >> 5;                // 0..127
        int kq = fl & 31;                // 16B unit within chunk
        const __nv_bfloat16* p = (m < 64)
            ? (sHi + (size_t)m * PU + kc + kq * 8)
            : (sLo + (size_t)(m - 64) * PU + kc + kq * 8);
        *(uint4*)(Abuf + m * AROWB + kq * 16) = *(const uint4*)p;
    }
}

// ---------------------------------------------------------------------------
// Kernel 2: persistent GRU scan on mma.sync bf16 tensor cores.
// Block owns N=24 (3 gates x 8 u). A[128,1024] = [h_hi;h_lo] (hi/lo bf16 split).
// Warps own k-slices: ktile_local = warp*2+{0,1} per 256-k chunk.
// acc += A_hi x (Whi + Wlo)  and  A_lo x Whi   (lo x lo dropped, ~1e-6 rel).
// Whi frags register-stationary (48 regs/warp); Wlo from padded smem.
// k-partials reduced via smem; epilogue: thread (b, u-pair) does gates.
// ---------------------------------------------------------------------------
__global__ __launch_bounds__(TPB, 1) void k_gru(
    const float* __restrict__ xp,
    const float* __restrict__ h0,
    const float* __restrict__ Wrec,
    const float* __restrict__ brec,
    float* __restrict__ out,
    float* __restrict__ hlast)
{
    extern __shared__ char sm[];
    const uint32_t smb = smem_u32(sm);
    const int tid   = threadIdx.x;
    const int warp  = tid >> 5;
    const int lane  = tid & 31;
    const int ubase = blockIdx.x * TILE_U;

    __nv_bfloat16* WloS = (__nv_bfloat16*)(sm + SM_WLO);
    float* os  = (float*)(sm + SM_OS);
    uint32_t* osh = (uint32_t*)(sm + SM_OSH);
    uint32_t* osl = (uint32_t*)(sm + SM_OSL);
    float* brs = (float*)(sm + SM_BRS);
    float* Dp  = (float*)sm;                  // overlay of A buffers

    // ---- one-time: Whi register fragments + Wlo smem + biases ----
    // Bh[kt8][nt][reg]: warp's 8 global ktiles = c*16 + warp*2 + j
    uint32_t Bh[8][3][2];
#pragma unroll
    for (int c = 0; c < 4; c++)
#pragma unroll
        for (int j = 0; j < 2; j++) {
            int KT = c * 16 + warp * 2 + j;
            int k0 = KT * 16 + (lane & 3) * 2;
#pragma unroll
            for (int nt = 0; nt < 3; nt++) {
                int n = nt * 8 + (lane >> 2);
                int col = (n >> 3) * PU + ubase + (n & 7);
                float w0 = Wrec[(size_t)k0 * PC3 + col];
                float w1 = Wrec[(size_t)(k0 + 1) * PC3 + col];
                float w8 = Wrec[(size_t)(k0 + 8) * PC3 + col];
                float w9 = Wrec[(size_t)(k0 + 9) * PC3 + col];
                Bh[c * 2 + j][nt][0] = pack_bf16x2(__bfloat162float(__float2bfloat16_rn(w0)),
                                                   __bfloat162float(__float2bfloat16_rn(w1)));
                Bh[c * 2 + j][nt][1] = pack_bf16x2(__bfloat162float(__float2bfloat16_rn(w8)),
                                                   __bfloat162float(__float2bfloat16_rn(w9)));
            }
        }
    for (int idx = tid; idx < NCOL * PU; idx += TPB) {
        int n = idx >> 10, k = idx & 1023;
        int col = (n >> 3) * PU + ubase + (n & 7);
        float w = Wrec[(size_t)k * PC3 + col];
        float whi = __bfloat162float(__float2bfloat16_rn(w));
        WloS[n * WLOST + k] = __float2bfloat16_rn(w - whi);
    }
    if (tid < NCOL) brs[tid] = brec[(tid >> 3) * PU + ubase + (tid & 7)];
    __syncthreads();

    const int eb  = tid >> 2;        // epilogue batch 0..63
    const int uo  = tid & 3;         // u-pair 0..3
    const uint32_t laneoff = (uint32_t)((lane & 15) * AROWB + (lane >> 4) * 16);

    for (int t = 0; t < PT; t++) {
        const int par = t & 1;
        const __nv_bfloat16* sHi = g_hhi[par];
        const __nv_bfloat16* sLo = g_hlo[par];
        __nv_bfloat16* dHi = g_hhi[par ^ 1];
        __nv_bfloat16* dLo = g_hlo[par ^ 1];

        // ---- epilogue operand prefetch (every thread: b=eb, u pair uo) ----
        const float* xrow = xp + ((size_t)t * PB + eb) * PC3 + ubase + uo * 2;
        float2 xz = *(const float2*)(xrow);
        float2 xr = *(const float2*)(xrow + PU);
        float2 xh = *(const float2*)(xrow + 2 * PU);
        float2 hp = (t == 0)
            ? *(const float2*)(h0 + (size_t)eb * PU + ubase + uo * 2)
            : *(const float2*)(out + ((size_t)eb * PT + (t - 1)) * PU + ubase + uo * 2);

        float acc[8][3][4];
#pragma unroll
        for (int mt = 0; mt < 8; mt++)
#pragma unroll
            for (int nt = 0; nt < 3; nt++)
#pragma unroll
                for (int r = 0; r < 4; r++) acc[mt][nt][r] = 0.f;

        stage_chunk(sm, sHi, sLo, 0, tid);
        __syncthreads();

#pragma unroll
        for (int c = 0; c < NCHNK; c++) {
            const uint32_t abase = smb + (uint32_t)((c & 1) * ABUFB);
#pragma unroll
            for (int j = 0; j < 2; j++) {
                const int ktl = warp * 2 + j;       // ktile within chunk
                const int KT  = c * 16 + ktl;       // global ktile
                // Wlo frags for this ktile
                uint32_t bl[3][2];
#pragma unroll
                for (int nt = 0; nt < 3; nt++) {
                    int n = nt * 8 + (lane >> 2);
                    const __nv_bfloat16* wl = WloS + n * WLOST + KT * 16 + (lane & 3) * 2;
                    bl[nt][0] = *(const uint32_t*)(wl);
                    bl[nt][1] = *(const uint32_t*)(wl + 8);
                }
#pragma unroll
                for (int mt = 0; mt < 8; mt++) {
                    uint32_t a[4];
                    ldsm_x4(a, abase + (uint32_t)(mt * 16 * AROWB + ktl * 32) + laneoff);
#pragma unroll
                    for (int nt = 0; nt < 3; nt++) {
                        mma_bf16(acc[mt][nt], a, Bh[c * 2 + j][nt]);
                        if (mt < 4) mma_bf16(acc[mt][nt], a, bl[nt]);
                    }
                }
            }
            if (c < NCHNK - 1)
                stage_chunk(sm + ((c + 1) & 1) * ABUFB, sHi, sLo, (c + 1) * KCHUNK, tid);
            __syncthreads();
        }

        // ---- write k-partials (overlay A buffers; MMA reads all done) ----
#pragma unroll
        for (int mt = 0; mt < 8; mt++)
#pragma unroll
            for (int nt = 0; nt < 3; nt++) {
                int m = mt * 16 + (lane >> 2);
                int n = nt * 8 + (lane & 3) * 2;
                *(float2*)&Dp[((warp << 7) + m) * NCOL + n] =
                    make_float2(acc[mt][nt][0], acc[mt][nt][1]);
                *(float2*)&Dp[((warp << 7) + m + 8) * NCOL + n] =
                    make_float2(acc[mt][nt][2], acc[mt][nt][3]);
            }
        __syncthreads();

        // ---- reduce 8 warps x (hi row + lo row), then gates ----
        {
            float s0 = 0.f, s1 = 0.f, s2 = 0.f, s3 = 0.f, s4 = 0.f, s5 = 0.f;
#pragma unroll
            for (int w = 0; w < 8; w++) {
#pragma unroll
                for (int rr = 0; rr < 2; rr++) {
                    const float* base = Dp + ((w << 7) + eb + rr * 64) * NCOL + uo * 2;
                    float2 vz = *(const float2*)(base);
                    float2 vr = *(const float2*)(base + 8);
                    float2 vh = *(const float2*)(base + 16);
                    s0 += vz.x; s1 += vz.y;
                    s2 += vr.x; s3 += vr.y;
                    s4 += vh.x; s5 += vh.y;
                }
            }
            int u0 = uo * 2;
            float z0 = sig_fast(xz.x + s0 + brs[u0]);
            float r0 = sig_fast(xr.x + s2 + brs[8 + u0]);
            float c0 = tanh_fast(xh.x + r0 * (s4 + brs[16 + u0]));
            float hn0 = z0 * hp.x + (1.f - z0) * c0;
            float z1 = sig_fast(xz.y + s1 + brs[u0 + 1]);
            float r1 = sig_fast(xr.y + s3 + brs[8 + u0 + 1]);
            float c1 = tanh_fast(xh.y + r1 * (s5 + brs[16 + u0 + 1]));
            float hn1 = z1 * hp.y + (1.f - z1) * c1;

            *(float2*)&os[eb * 8 + u0] = make_float2(hn0, hn1);
            __nv_bfloat16 h0b = __float2bfloat16_rn(hn0);
            __nv_bfloat16 h1b = __float2bfloat16_rn(hn1);
            osh[eb * 4 + uo] = pack_bf16x2(__bfloat162float(h0b), __bfloat162float(h1b));
            osl[eb * 4 + uo] = pack_bf16x2(hn0 - __bfloat162float(h0b),
                                           hn1 - __bfloat162float(h1b));
        }
        __syncthreads();

        // ---- coalesced copy-out: out, hlast, next-step h splits ----
        if (tid < 128) {
            int bb = tid >> 1, hf = tid & 1;
            float4 v = *(const float4*)&os[bb * 8 + hf * 4];
            *(float4*)(out + ((size_t)bb * PT + t) * PU + ubase + hf * 4) = v;
            if (t == PT - 1 && hlast != nullptr)
                *(float4*)(hlast + (size_t)bb * PU + ubase + hf * 4) = v;
            uint2 vh = *(const uint2*)&osh[bb * 4 + hf * 2];
            uint2 vl = *(const uint2*)&osl[bb * 4 + hf * 2];
            *(uint2*)(dHi + (size_t)bb * PU + ubase + hf * 4) = vh;
            *(uint2*)(dLo + (size_t)bb * PU + ubase + hf * 4) = vl;
        }

        grid_barrier(NBLK);
    }
}

// ---------------------------------------------------------------------------
// launch
// ---------------------------------------------------------------------------
extern "C" void kernel_launch(void* const* d_in, const int* in_sizes, int n_in,
                              void* d_out, int out_size)
{
    const int*   x       = (const int*)  d_in[0];
    const float* initial = (const float*)d_in[1];
    const float* emb     = (const float*)d_in[2];
    const float* Win     = (const float*)d_in[3];
    const float* Wrec    = (const float*)d_in[4];
    const float* bin     = (const float*)d_in[5];
    const float* brec    = (const float*)d_in[6];

    float* out = (float*)d_out;
    float* hlast = nullptr;
    const long long n_outputs = (long long)PB * PT * PU;
    if ((long long)out_size >= n_outputs + (long long)PB * PU) {
        hlast = out + (size_t)n_outputs;
    }

    float* xp = nullptr;
    cudaGetSymbolAddress((void**)&xp, g_xp);
    __nv_bfloat16* hhi = nullptr;
    __nv_bfloat16* hlo = nullptr;
    cudaGetSymbolAddress((void**)&hhi, g_hhi);
    cudaGetSymbolAddress((void**)&hlo, g_hlo);

    // split initial state into parity-0 buffers
    k_split_init<<<(PB * PU + 255) / 256, 256>>>(initial, hhi, hlo);

    // GEMM1: embedding gather + input projection
    dim3 g1(PC3 / 128, (PT * PB) / 128);
    k_inproj<<<g1, 256>>>(x, emb, Win, bin, xp);

    // tensor-core (mma.sync) GRU scan
    cudaFuncSetAttribute(k_gru, cudaFuncAttributeMaxDynamicSharedMemorySize, SM_TOTAL);
    k_gru<<<NBLK, TPB, SM_TOTAL>>>(xp, initial, Wrec, brec, out, hlast);
}

// round 9
// speedup vs baseline: 4.8692x; 1.0377x over previous
#include <cuda_runtime.h>
#include <cuda_bf16.h>
#include <math.h>
#include <stdint.h>

// Problem dims
#define PB 64
#define PT 1024
#define PE 256
#define PU 1024
#define PC3 3072
#define PV 32000

#define NBLK 128
#define TILE_U 8          // u per block; N = 24 cols (3 gates x 8 u)
#define TPB 256           // 8 warps
#define NCOL 24
#define KCHUNK 256        // k per staged A chunk (scan)
#define NCHNK (PU / KCHUNK)
#define AROWB 528         // scan A smem row stride bytes
#define ABUFB (128 * AROWB)
#define WLOST 1032        // Wlo smem row stride (bf16 elems)
#define DPST 26           // Dp row stride (floats) — conflict-reduced

// scan smem byte offsets
#define SM_A     0
#define SM_WLO   (2 * ABUFB)             // 135168
#define SM_OS    184704
#define SM_OSH   186752
#define SM_OSL   187776
#define SM_BRS   188800
#define SM_TOTAL 188928
// Dp overlays A buffers: 8 * 128 * DPST * 4 = 106496 <= 135168

// inproj-mma smem (per buffer): AH 0, AL 10240, BH 20480, BL 30720; buf=40960
#define IP_BUF   40960
#define IP_TOTAL (2 * IP_BUF)
#define IPROW 80           // 40 bf16 row stride

// ---------------------------------------------------------------------------
// global scratch
// ---------------------------------------------------------------------------
__device__ float g_xp[(size_t)PT * PB * PC3];
__device__ __nv_bfloat16 g_hhi[2][PB * PU];
__device__ __nv_bfloat16 g_hlo[2][PB * PU];
__device__ __nv_bfloat16 g_embh[(size_t)PV * PE];
__device__ __nv_bfloat16 g_embl[(size_t)PV * PE];
__device__ __nv_bfloat16 g_winth[(size_t)PC3 * PE];   // transposed [n][k]
__device__ __nv_bfloat16 g_wintl[(size_t)PC3 * PE];

__device__ unsigned g_bar_count = 0;
__device__ unsigned g_bar_gen = 0;

__device__ __forceinline__ void grid_barrier(unsigned nb) {
    __syncthreads();
    if (threadIdx.x == 0) {
        __threadfence();
        unsigned g = *((volatile unsigned*)&g_bar_gen);
        unsigned prev = atomicAdd(&g_bar_count, 1u);
        if (prev == nb - 1u) {
            atomicExch(&g_bar_count, 0u);
            __threadfence();
            atomicAdd(&g_bar_gen, 1u);
        } else {
            while (*((volatile unsigned*)&g_bar_gen) == g) { }
            __threadfence();
        }
    }
    __syncthreads();
}

// ---------------------------------------------------------------------------
// PTX wrappers (baseline PTX, valid on compute_103)
// ---------------------------------------------------------------------------
__device__ __forceinline__ uint32_t smem_u32(const void* p) {
    uint32_t a;
    asm("{ .reg .u64 t; cvta.to.shared.u64 t, %1; cvt.u32.u64 %0, t; }" : "=r"(a) : "l"(p));
    return a;
}
__device__ __forceinline__ void mma_bf16(float* d, const uint32_t* a, const uint32_t* b) {
    asm volatile(
        "mma.sync.aligned.m16n8k16.row.col.f32.bf16.bf16.f32 "
        "{%0,%1,%2,%3}, {%4,%5,%6,%7}, {%8,%9}, {%0,%1,%2,%3};"
        : "+f"(d[0]), "+f"(d[1]), "+f"(d[2]), "+f"(d[3])
        : "r"(a[0]), "r"(a[1]), "r"(a[2]), "r"(a[3]), "r"(b[0]), "r"(b[1]));
}
__device__ __forceinline__ void ldsm_x4(uint32_t* r, uint32_t addr) {
    asm volatile("ldmatrix.sync.aligned.m8n8.x4.shared.b16 {%0,%1,%2,%3}, [%4];"
                 : "=r"(r[0]), "=r"(r[1]), "=r"(r[2]), "=r"(r[3]) : "r"(addr));
}
__device__ __forceinline__ void cp16(uint32_t dst, const void* src) {
    asm volatile("cp.async.cg.shared.global [%0], [%1], 16;" :: "r"(dst), "l"(src));
}
__device__ __forceinline__ void cp_commit() { asm volatile("cp.async.commit_group;" ::: "memory"); }
__device__ __forceinline__ void cp_wait0()  { asm volatile("cp.async.wait_group 0;" ::: "memory"); }
__device__ __forceinline__ uint32_t pack_bf16x2(float lo, float hi) {
    __nv_bfloat162 v = __floats2bfloat162_rn(lo, hi);
    return *(uint32_t*)&v;
}
__device__ __forceinline__ float sig_fast(float v) {
    return 1.0f / (1.0f + __expf(-v));
}
__device__ __forceinline__ float tanh_fast(float v) {
    float ax = fabsf(v);
    float e  = __expf(2.0f * ax);
    float t  = 1.0f - 2.0f / (e + 1.0f);
    return copysignf(t, v);
}

// ---------------------------------------------------------------------------
// prep kernels: bf16 hi/lo splits
// ---------------------------------------------------------------------------
__global__ void k_split_init(const float* __restrict__ h0,
                             __nv_bfloat16* __restrict__ hi,
                             __nv_bfloat16* __restrict__ lo) {
    int idx = blockIdx.x * blockDim.x + threadIdx.x;
    if (idx < PB * PU) {
        float v = h0[idx];
        __nv_bfloat16 h = __float2bfloat16_rn(v);
        hi[idx] = h;
        lo[idx] = __float2bfloat16_rn(v - __bfloat162float(h));
    }
}

__global__ void k_prep_emb(const float* __restrict__ emb,
                           __nv_bfloat16* __restrict__ hi,
                           __nv_bfloat16* __restrict__ lo) {
    size_t i4 = (size_t)blockIdx.x * blockDim.x + threadIdx.x;
    if (i4 < (size_t)PV * PE / 4) {
        float4 v = ((const float4*)emb)[i4];
        __nv_bfloat16 h[4], l[4];
        float f[4] = {v.x, v.y, v.z, v.w};
#pragma unroll
        for (int j = 0; j < 4; j++) {
            h[j] = __float2bfloat16_rn(f[j]);
            l[j] = __float2bfloat16_rn(f[j] - __bfloat162float(h[j]));
        }
        ((uint2*)hi)[i4] = *(uint2*)h;
        ((uint2*)lo)[i4] = *(uint2*)l;
    }
}

__global__ void k_prep_winT(const float* __restrict__ Win,
                            __nv_bfloat16* __restrict__ hi,
                            __nv_bfloat16* __restrict__ lo) {
    int idx = blockIdx.x * blockDim.x + threadIdx.x;   // over PE*PC3, coalesced read
    if (idx < PE * PC3) {
        int k = idx / PC3, n = idx - k * PC3;
        float w = Win[idx];
        __nv_bfloat16 h = __float2bfloat16_rn(w);
        hi[(size_t)n * PE + k] = h;
        lo[(size_t)n * PE + k] = __float2bfloat16_rn(w - __bfloat162float(h));
    }
}

// ---------------------------------------------------------------------------
// Kernel 1: xp = emb[x] @ W_in + b_in on mma.sync bf16 (3-product hi/lo).
// BM=128, BN=128, BK=32, 8 warps (2m x 4n), warp tile 64x32.
// A gathered from split emb tables; B from pre-transposed split W_in [n][k].
// ---------------------------------------------------------------------------
__global__ __launch_bounds__(256) void k_inproj_mma(
    const int* __restrict__ x,
    const __nv_bfloat16* __restrict__ embH,
    const __nv_bfloat16* __restrict__ embL,
    const __nv_bfloat16* __restrict__ winH,
    const __nv_bfloat16* __restrict__ winL,
    const float* __restrict__ bin,
    float* __restrict__ xp)
{
    extern __shared__ char sm2[];
    __shared__ int rowIdx[128];
    const uint32_t smb = smem_u32(sm2);
    const int tid  = threadIdx.x;
    const int warp = tid >> 5;
    const int lane = tid & 31;
    const int wm = warp & 1;       // 0..1 (64 rows each)
    const int wn = warp >> 1;      // 0..3 (32 cols each)
    const int m0 = blockIdx.y * 128;
    const int n0 = blockIdx.x * 128;

    if (tid < 128) {
        int m = m0 + tid;
        rowIdx[tid] = x[(size_t)(m & 63) * PT + (m >> 6)];
    }
    __syncthreads();

    float acc[4][4][4];
#pragma unroll
    for (int i = 0; i < 4; i++)
#pragma unroll
        for (int j = 0; j < 4; j++)
#pragma unroll
            for (int r = 0; r < 4; r++) acc[i][j][r] = 0.f;

    float2 bv[4];
#pragma unroll
    for (int nt = 0; nt < 4; nt++) {
        int ng = n0 + wn * 32 + nt * 8 + (lane & 3) * 2;
        bv[nt] = *(const float2*)(bin + ng);
    }

    // staging lambda-ish macro: one BK=32 chunk into buffer `buf`
    auto stage = [&](int buf, int c) {
        uint32_t base = smb + buf * IP_BUF;
        int kt0 = c * 32;
#pragma unroll
        for (int i = 0; i < 2; i++) {
            int fl = tid + i * 256;
            int m = fl >> 2, kq = fl & 3;
            const __nv_bfloat16* sh = embH + (size_t)rowIdx[m] * PE + kt0 + kq * 8;
            const __nv_bfloat16* sl = embL + (size_t)rowIdx[m] * PE + kt0 + kq * 8;
            cp16(base + m * IPROW + kq * 16, sh);
            cp16(base + 10240 + m * IPROW + kq * 16, sl);
            const __nv_bfloat16* bh = winH + (size_t)(n0 + m) * PE + kt0 + kq * 8;
            const __nv_bfloat16* bl = winL + (size_t)(n0 + m) * PE + kt0 + kq * 8;
            cp16(base + 20480 + m * IPROW + kq * 16, bh);
            cp16(base + 30720 + m * IPROW + kq * 16, bl);
        }
    };

    stage(0, 0); cp_commit();
#pragma unroll 1
    for (int c = 0; c < 8; c++) {
        cp_wait0();
        __syncthreads();
        if (c < 7) { stage((c + 1) & 1, c + 1); cp_commit(); }
        uint32_t base = smb + (c & 1) * IP_BUF;
#pragma unroll
        for (int kt = 0; kt < 2; kt++) {
            uint32_t bh[4][2], bl[4][2];
#pragma unroll
            for (int nt = 0; nt < 4; nt++) {
                uint32_t a = base + 20480 +
                    (uint32_t)((wn * 32 + nt * 8 + (lane >> 2)) * IPROW + kt * 32 + (lane & 3) * 4);
                asm volatile("ld.shared.b32 %0, [%1];" : "=r"(bh[nt][0]) : "r"(a));
                asm volatile("ld.shared.b32 %0, [%1];" : "=r"(bh[nt][1]) : "r"(a + 16));
                asm volatile("ld.shared.b32 %0, [%1];" : "=r"(bl[nt][0]) : "r"(a + 10240));
                asm volatile("ld.shared.b32 %0, [%1];" : "=r"(bl[nt][1]) : "r"(a + 10240 + 16));
            }
            uint32_t ah[4][4], al[4][4];
#pragma unroll
            for (int mt = 0; mt < 4; mt++) {
                uint32_t a = base +
                    (uint32_t)((wm * 64 + mt * 16 + (lane & 15)) * IPROW + (lane >> 4) * 16 + kt * 32);
                ldsm_x4(ah[mt], a);
                ldsm_x4(al[mt], a + 10240);
            }
#pragma unroll
            for (int mt = 0; mt < 4; mt++)
#pragma unroll
                for (int nt = 0; nt < 4; nt++) mma_bf16(acc[mt][nt], ah[mt], bh[nt]);
#pragma unroll
            for (int mt = 0; mt < 4; mt++)
#pragma unroll
                for (int nt = 0; nt < 4; nt++) mma_bf16(acc[mt][nt], ah[mt], bl[nt]);
#pragma unroll
            for (int mt = 0; mt < 4; mt++)
#pragma unroll
                for (int nt = 0; nt < 4; nt++) mma_bf16(acc[mt][nt], al[mt], bh[nt]);
        }
    }

#pragma unroll
    for (int mt = 0; mt < 4; mt++) {
        int mg = m0 + wm * 64 + mt * 16 + (lane >> 2);
#pragma unroll
        for (int nt = 0; nt < 4; nt++) {
            int ng = n0 + wn * 32 + nt * 8 + (lane & 3) * 2;
            *(float2*)(xp + (size_t)mg * PC3 + ng) =
                make_float2(acc[mt][nt][0] + bv[nt].x, acc[mt][nt][1] + bv[nt].y);
            *(float2*)(xp + (size_t)(mg + 8) * PC3 + ng) =
                make_float2(acc[mt][nt][2] + bv[nt].x, acc[mt][nt][3] + bv[nt].y);
        }
    }
}

// ---------------------------------------------------------------------------
// Kernel 2: persistent GRU scan (mma.sync, cp.async staging, post-barrier out)
// ---------------------------------------------------------------------------
__global__ __launch_bounds__(TPB, 1) void k_gru(
    const float* __restrict__ xp,
    const float* __restrict__ h0,
    const float* __restrict__ Wrec,
    const float* __restrict__ brec,
    float* __restrict__ out,
    float* __restrict__ hlast)
{
    extern __shared__ char sm[];
    const uint32_t smb = smem_u32(sm);
    const int tid   = threadIdx.x;
    const int warp  = tid >> 5;
    const int lane  = tid & 31;
    const int ubase = blockIdx.x * TILE_U;

    __nv_bfloat16* WloS = (__nv_bfloat16*)(sm + SM_WLO);
    float* os  = (float*)(sm + SM_OS);
    uint32_t* osh = (uint32_t*)(sm + SM_OSH);
    uint32_t* osl = (uint32_t*)(sm + SM_OSL);
    float* brs = (float*)(sm + SM_BRS);
    float* Dp  = (float*)sm;

    // Whi register fragments: warp's 8 ktiles = c*16 + warp*2 + j
    uint32_t Bh[8][3][2];
#pragma unroll
    for (int c = 0; c < 4; c++)
#pragma unroll
        for (int j = 0; j < 2; j++) {
            int KT = c * 16 + warp * 2 + j;
            int k0 = KT * 16 + (lane & 3) * 2;
#pragma unroll
            for (int nt = 0; nt < 3; nt++) {
                int n = nt * 8 + (lane >> 2);
                int col = (n >> 3) * PU + ubase + (n & 7);
                float w0 = Wrec[(size_t)k0 * PC3 + col];
                float w1 = Wrec[(size_t)(k0 + 1) * PC3 + col];
                float w8 = Wrec[(size_t)(k0 + 8) * PC3 + col];
                float w9 = Wrec[(size_t)(k0 + 9) * PC3 + col];
                Bh[c * 2 + j][nt][0] = pack_bf16x2(__bfloat162float(__float2bfloat16_rn(w0)),
                                                   __bfloat162float(__float2bfloat16_rn(w1)));
                Bh[c * 2 + j][nt][1] = pack_bf16x2(__bfloat162float(__float2bfloat16_rn(w8)),
                                                   __bfloat162float(__float2bfloat16_rn(w9)));
            }
        }
    for (int idx = tid; idx < NCOL * PU; idx += TPB) {
        int n = idx >> 10, k = idx & 1023;
        int col = (n >> 3) * PU + ubase + (n & 7);
        float w = Wrec[(size_t)k * PC3 + col];
        float whi = __bfloat162float(__float2bfloat16_rn(w));
        WloS[n * WLOST + k] = __float2bfloat16_rn(w - whi);
    }
    if (tid < NCOL) brs[tid] = brec[(tid >> 3) * PU + ubase + (tid & 7)];
    __syncthreads();

    const int eb = tid >> 2;         // epilogue batch 0..63
    const int uo = tid & 3;          // u-pair 0..3
    const uint32_t laneoff = (uint32_t)((lane & 15) * AROWB + (lane >> 4) * 16);

    for (int t = 0; t < PT; t++) {
        const int par = t & 1;
        const __nv_bfloat16* sHi = g_hhi[par];
        const __nv_bfloat16* sLo = g_hlo[par];
        __nv_bfloat16* dHi = g_hhi[par ^ 1];
        __nv_bfloat16* dLo = g_hlo[par ^ 1];

        // epilogue operand prefetch; hp from smem os (own block's slice)
        const float* xrow = xp + ((size_t)t * PB + eb) * PC3 + ubase + uo * 2;
        float2 xz = *(const float2*)(xrow);
        float2 xr = *(const float2*)(xrow + PU);
        float2 xh = *(const float2*)(xrow + 2 * PU);
        float2 hp = (t == 0)
            ? *(const float2*)(h0 + (size_t)eb * PU + ubase + uo * 2)
            : *(const float2*)&os[eb * 8 + uo * 2];

        float acc[8][3][4];
#pragma unroll
        for (int mt = 0; mt < 8; mt++)
#pragma unroll
            for (int nt = 0; nt < 3; nt++)
#pragma unroll
                for (int r = 0; r < 4; r++) acc[mt][nt][r] = 0.f;

        // ---- pipelined staging (cp.async) + MMA ----
        {
#pragma unroll
            for (int i = 0; i < 16; i++) {
                int fl = tid + i * TPB;
                int m = fl >> 5, kq = fl & 31;
                const __nv_bfloat16* p = (m < 64)
                    ? (sHi + (size_t)m * PU + kq * 8)
                    : (sLo + (size_t)(m - 64) * PU + kq * 8);
                cp16(smb + (uint32_t)(m * AROWB + kq * 16), p);
            }
            cp_commit();
        }
#pragma unroll 1
        for (int c = 0; c < NCHNK; c++) {
            cp_wait0();
            __syncthreads();
            if (c < NCHNK - 1) {
                uint32_t nb = smb + (uint32_t)(((c + 1) & 1) * ABUFB);
                int kc = (c + 1) * KCHUNK;
#pragma unroll
                for (int i = 0; i < 16; i++) {
                    int fl = tid + i * TPB;
                    int m = fl >> 5, kq = fl & 31;
                    const __nv_bfloat16* p = (m < 64)
                        ? (sHi + (size_t)m * PU + kc + kq * 8)
                        : (sLo + (size_t)(m - 64) * PU + kc + kq * 8);
                    cp16(nb + (uint32_t)(m * AROWB + kq * 16), p);
                }
                cp_commit();
            }
            const uint32_t abase = smb + (uint32_t)((c & 1) * ABUFB);
#pragma unroll
            for (int j = 0; j < 2; j++) {
                const int ktl = warp * 2 + j;
                const int KT  = c * 16 + ktl;
                uint32_t bl[3][2];
#pragma unroll
                for (int nt = 0; nt < 3; nt++) {
                    int n = nt * 8 + (lane >> 2);
                    const __nv_bfloat16* wl = WloS + n * WLOST + KT * 16 + (lane & 3) * 2;
                    bl[nt][0] = *(const uint32_t*)(wl);
                    bl[nt][1] = *(const uint32_t*)(wl + 8);
                }
#pragma unroll
                for (int mt = 0; mt < 8; mt++) {
                    uint32_t a[4];
                    ldsm_x4(a, abase + (uint32_t)(mt * 16 * AROWB + ktl * 32) + laneoff);
#pragma unroll
                    for (int nt = 0; nt < 3; nt++) mma_bf16(acc[mt][nt], a, Bh[c * 2 + j][nt]);
                    if (mt < 4) {
#pragma unroll
                        for (int nt = 0; nt < 3; nt++) mma_bf16(acc[mt][nt], a, bl[nt]);
                    }
                }
            }
        }

        // ---- k-partials to smem (overlay A) ----
        __syncthreads();
#pragma unroll
        for (int mt = 0; mt < 8; mt++)
#pragma unroll
            for (int nt = 0; nt < 3; nt++) {
                int m = mt * 16 + (lane >> 2);
                int n = nt * 8 + (lane & 3) * 2;
                *(float2*)&Dp[((warp << 7) + m) * DPST + n] =
                    make_float2(acc[mt][nt][0], acc[mt][nt][1]);
                *(float2*)&Dp[((warp << 7) + m + 8) * DPST + n] =
                    make_float2(acc[mt][nt][2], acc[mt][nt][3]);
            }
        __syncthreads();

        // ---- reduce + gates ----
        {
            float s0 = 0.f, s1 = 0.f, s2 = 0.f, s3 = 0.f, s4 = 0.f, s5 = 0.f;
#pragma unroll
            for (int w = 0; w < 8; w++) {
#pragma unroll
                for (int rr = 0; rr < 2; rr++) {
                    const float* base = Dp + ((w << 7) + eb + rr * 64) * DPST + uo * 2;
                    float2 vz = *(const float2*)(base);
                    float2 vr = *(const float2*)(base + 8);
                    float2 vh = *(const float2*)(base + 16);
                    s0 += vz.x; s1 += vz.y;
                    s2 += vr.x; s3 += vr.y;
                    s4 += vh.x; s5 += vh.y;
                }
            }
            int u0 = uo * 2;
            float z0 = sig_fast(xz.x + s0 + brs[u0]);
            float r0 = sig_fast(xr.x + s2 + brs[8 + u0]);
            float c0 = tanh_fast(xh.x + r0 * (s4 + brs[16 + u0]));
            float hn0 = z0 * hp.x + (1.f - z0) * c0;
            float z1 = sig_fast(xz.y + s1 + brs[u0 + 1]);
            float r1 = sig_fast(xr.y + s3 + brs[8 + u0 + 1]);
            float c1 = tanh_fast(xh.y + r1 * (s5 + brs[16 + u0 + 1]));
            float hn1 = z1 * hp.y + (1.f - z1) * c1;

            *(float2*)&os[eb * 8 + u0] = make_float2(hn0, hn1);
            __nv_bfloat16 h0b = __float2bfloat16_rn(hn0);
            __nv_bfloat16 h1b = __float2bfloat16_rn(hn1);
            osh[eb * 4 + uo] = pack_bf16x2(__bfloat162float(h0b), __bfloat162float(h1b));
            osl[eb * 4 + uo] = pack_bf16x2(hn0 - __bfloat162float(h0b),
                                           hn1 - __bfloat162float(h1b));
        }
        __syncthreads();

        // ---- publish next-step h splits (cross-block critical path) ----
        if (tid < 128) {
            int bb = tid >> 1, hf = tid & 1;
            uint2 vh = *(const uint2*)&osh[bb * 4 + hf * 2];
            uint2 vl = *(const uint2*)&osl[bb * 4 + hf * 2];
            *(uint2*)(dHi + (size_t)bb * PU + ubase + hf * 4) = vh;
            *(uint2*)(dLo + (size_t)bb * PU + ubase + hf * 4) = vl;
        }

        grid_barrier(NBLK);

        // ---- out/hlast write: off peers' critical path, overlaps next step ----
        if (tid < 128) {
            int bb = tid >> 1, hf = tid & 1;
            float4 v = *(const float4*)&os[bb * 8 + hf * 4];
            *(float4*)(out + ((size_t)bb * PT + t) * PU + ubase + hf * 4) = v;
            if (t == PT - 1 && hlast != nullptr)
                *(float4*)(hlast + (size_t)bb * PU + ubase + hf * 4) = v;
        }
    }
}

// ---------------------------------------------------------------------------
// launch
// ---------------------------------------------------------------------------
extern "C" void kernel_launch(void* const* d_in, const int* in_sizes, int n_in,
                              void* d_out, int out_size)
{
    const int*   x       = (const int*)  d_in[0];
    const float* initial = (const float*)d_in[1];
    const float* emb     = (const float*)d_in[2];
    const float* Win     = (const float*)d_in[3];
    const float* Wrec    = (const float*)d_in[4];
    const float* bin     = (const float*)d_in[5];
    const float* brec    = (const float*)d_in[6];

    float* out = (float*)d_out;
    float* hlast = nullptr;
    const long long n_outputs = (long long)PB * PT * PU;
    if ((long long)out_size >= n_outputs + (long long)PB * PU) {
        hlast = out + (size_t)n_outputs;
    }

    float* xp = nullptr;
    cudaGetSymbolAddress((void**)&xp, g_xp);
    __nv_bfloat16 *hhi, *hlo, *embh, *embl, *winth, *wintl;
    cudaGetSymbolAddress((void**)&hhi, g_hhi);
    cudaGetSymbolAddress((void**)&hlo, g_hlo);
    cudaGetSymbolAddress((void**)&embh, g_embh);
    cudaGetSymbolAddress((void**)&embl, g_embl);
    cudaGetSymbolAddress((void**)&winth, g_winth);
    cudaGetSymbolAddress((void**)&wintl, g_wintl);

    // prep: splits + transpose
    k_split_init<<<(PB * PU + 255) / 256, 256>>>(initial, hhi, hlo);
    k_prep_emb<<<(int)(((size_t)PV * PE / 4 + 255) / 256), 256>>>(emb, embh, embl);
    k_prep_winT<<<(PE * PC3 + 255) / 256, 256>>>(Win, winth, wintl);

    // GEMM1 on tensor cores
    cudaFuncSetAttribute(k_inproj_mma, cudaFuncAttributeMaxDynamicSharedMemorySize, IP_TOTAL);
    dim3 g1(PC3 / 128, (PT * PB) / 128);
    k_inproj_mma<<<g1, 256, IP_TOTAL>>>(x, embh, embl, winth, wintl, bin, xp);

    // persistent GRU scan
    cudaFuncSetAttribute(k_gru, cudaFuncAttributeMaxDynamicSharedMemorySize, SM_TOTAL);
    k_gru<<<NBLK, TPB, SM_TOTAL>>>(xp, initial, Wrec, brec, out, hlast);
}

// round 10
// speedup vs baseline: 4.9496x; 1.0165x over previous
#include <cuda_runtime.h>
#include <cuda_bf16.h>
#include <math.h>
#include <stdint.h>

// Problem dims
#define PB 64
#define PT 1024
#define PE 256
#define PU 1024
#define PC3 3072
#define PV 32000

#define NBLK 128
#define TILE_U 8          // u per block; N = 24 cols (3 gates x 8 u)
#define TPB 256           // 8 warps
#define NCOL 24
#define KCHUNK 256        // k per staged A chunk (scan)
#define NCHNK (PU / KCHUNK)
#define AROWB 528         // scan A smem row stride bytes
#define ABUFB (128 * AROWB)
#define WLOST 1032        // Wlo smem row stride (bf16 elems)
#define DPST 26           // Dp row stride (floats), conflict-reduced

// scan smem byte offsets
#define SM_A     0
#define SM_WLO   (2 * ABUFB)             // 135168
#define SM_OS    184704
#define SM_OSH   186752
#define SM_OSL   187776
#define SM_BRS   188800
#define SM_TOTAL 188928
// Dp overlays A buffers: 1024 * DPST * 4 = 106496 <= 135168

// inproj-mma smem
#define IP_BUF   40960
#define IP_TOTAL (2 * IP_BUF)
#define IPROW 80

// ---------------------------------------------------------------------------
// global scratch
// ---------------------------------------------------------------------------
__device__ float g_xp[(size_t)PT * PB * PC3];
__device__ __nv_bfloat16 g_hhi[2][PB * PU];
__device__ __nv_bfloat16 g_hlo[2][PB * PU];
__device__ __nv_bfloat16 g_embh[(size_t)PV * PE];
__device__ __nv_bfloat16 g_embl[(size_t)PV * PE];
__device__ __nv_bfloat16 g_winth[(size_t)PC3 * PE];
__device__ __nv_bfloat16 g_wintl[(size_t)PC3 * PE];

__device__ unsigned g_bar_count = 0;
__device__ unsigned g_bar_gen = 0;

// ---------------------------------------------------------------------------
// PTX wrappers (baseline PTX, valid on compute_103)
// ---------------------------------------------------------------------------
__device__ __forceinline__ uint32_t smem_u32(const void* p) {
    uint32_t a;
    asm("{ .reg .u64 t; cvta.to.shared.u64 t, %1; cvt.u32.u64 %0, t; }" : "=r"(a) : "l"(p));
    return a;
}
__device__ __forceinline__ void mma_bf16(float* d, const uint32_t* a, const uint32_t* b) {
    asm volatile(
        "mma.sync.aligned.m16n8k16.row.col.f32.bf16.bf16.f32 "
        "{%0,%1,%2,%3}, {%4,%5,%6,%7}, {%8,%9}, {%0,%1,%2,%3};"
        : "+f"(d[0]), "+f"(d[1]), "+f"(d[2]), "+f"(d[3])
        : "r"(a[0]), "r"(a[1]), "r"(a[2]), "r"(a[3]), "r"(b[0]), "r"(b[1]));
}
__device__ __forceinline__ void ldsm_x4(uint32_t* r, uint32_t addr) {
    asm volatile("ldmatrix.sync.aligned.m8n8.x4.shared.b16 {%0,%1,%2,%3}, [%4];"
                 : "=r"(r[0]), "=r"(r[1]), "=r"(r[2]), "=r"(r[3]) : "r"(addr));
}
__device__ __forceinline__ void cp16(uint32_t dst, const void* src) {
    asm volatile("cp.async.cg.shared.global [%0], [%1], 16;" :: "r"(dst), "l"(src));
}
__device__ __forceinline__ void cp_commit() { asm volatile("cp.async.commit_group;" ::: "memory"); }
__device__ __forceinline__ void cp_wait0()  { asm volatile("cp.async.wait_group 0;" ::: "memory"); }
__device__ __forceinline__ uint32_t pack_bf16x2(float lo, float hi) {
    __nv_bfloat162 v = __floats2bfloat162_rn(lo, hi);
    return *(uint32_t*)&v;
}
__device__ __forceinline__ float sig_fast(float v) {
    return 1.0f / (1.0f + __expf(-v));
}
__device__ __forceinline__ float tanh_fast(float v) {
    float ax = fabsf(v);
    float e  = __expf(2.0f * ax);
    float t  = 1.0f - 2.0f / (e + 1.0f);
    return copysignf(t, v);
}

// ---------------------------------------------------------------------------
// prep kernels
// ---------------------------------------------------------------------------
__global__ void k_split_init(const float* __restrict__ h0,
                             __nv_bfloat16* __restrict__ hi,
                             __nv_bfloat16* __restrict__ lo) {
    int idx = blockIdx.x * blockDim.x + threadIdx.x;
    if (idx < PB * PU) {
        float v = h0[idx];
        __nv_bfloat16 h = __float2bfloat16_rn(v);
        hi[idx] = h;
        lo[idx] = __float2bfloat16_rn(v - __bfloat162float(h));
    }
}

__global__ void k_prep_emb(const float* __restrict__ emb,
                           __nv_bfloat16* __restrict__ hi,
                           __nv_bfloat16* __restrict__ lo) {
    size_t i4 = (size_t)blockIdx.x * blockDim.x + threadIdx.x;
    if (i4 < (size_t)PV * PE / 4) {
        float4 v = ((const float4*)emb)[i4];
        __nv_bfloat16 h[4], l[4];
        float f[4] = {v.x, v.y, v.z, v.w};
#pragma unroll
        for (int j = 0; j < 4; j++) {
            h[j] = __float2bfloat16_rn(f[j]);
            l[j] = __float2bfloat16_rn(f[j] - __bfloat162float(h[j]));
        }
        ((uint2*)hi)[i4] = *(uint2*)h;
        ((uint2*)lo)[i4] = *(uint2*)l;
    }
}

__global__ void k_prep_winT(const float* __restrict__ Win,
                            __nv_bfloat16* __restrict__ hi,
                            __nv_bfloat16* __restrict__ lo) {
    int idx = blockIdx.x * blockDim.x + threadIdx.x;
    if (idx < PE * PC3) {
        int k = idx / PC3, n = idx - k * PC3;
        float w = Win[idx];
        __nv_bfloat16 h = __float2bfloat16_rn(w);
        hi[(size_t)n * PE + k] = h;
        lo[(size_t)n * PE + k] = __float2bfloat16_rn(w - __bfloat162float(h));
    }
}

// ---------------------------------------------------------------------------
// Kernel 1: xp = emb[x] @ W_in + b_in on mma.sync bf16 (3-product hi/lo).
// ---------------------------------------------------------------------------
__global__ __launch_bounds__(256) void k_inproj_mma(
    const int* __restrict__ x,
    const __nv_bfloat16* __restrict__ embH,
    const __nv_bfloat16* __restrict__ embL,
    const __nv_bfloat16* __restrict__ winH,
    const __nv_bfloat16* __restrict__ winL,
    const float* __restrict__ bin,
    float* __restrict__ xp)
{
    extern __shared__ char sm2[];
    __shared__ int rowIdx[128];
    const uint32_t smb = smem_u32(sm2);
    const int tid  = threadIdx.x;
    const int warp = tid >> 5;
    const int lane = tid & 31;
    const int wm = warp & 1;
    const int wn = warp >> 1;
    const int m0 = blockIdx.y * 128;
    const int n0 = blockIdx.x * 128;

    if (tid < 128) {
        int m = m0 + tid;
        rowIdx[tid] = x[(size_t)(m & 63) * PT + (m >> 6)];
    }
    __syncthreads();

    float acc[4][4][4];
#pragma unroll
    for (int i = 0; i < 4; i++)
#pragma unroll
        for (int j = 0; j < 4; j++)
#pragma unroll
            for (int r = 0; r < 4; r++) acc[i][j][r] = 0.f;

    float2 bv[4];
#pragma unroll
    for (int nt = 0; nt < 4; nt++) {
        int ng = n0 + wn * 32 + nt * 8 + (lane & 3) * 2;
        bv[nt] = *(const float2*)(bin + ng);
    }

    auto stage = [&](int buf, int c) {
        uint32_t base = smb + buf * IP_BUF;
        int kt0 = c * 32;
#pragma unroll
        for (int i = 0; i < 2; i++) {
            int fl = tid + i * 256;
            int m = fl >> 2, kq = fl & 3;
            const __nv_bfloat16* sh = embH + (size_t)rowIdx[m] * PE + kt0 + kq * 8;
            const __nv_bfloat16* sl = embL + (size_t)rowIdx[m] * PE + kt0 + kq * 8;
            cp16(base + m * IPROW + kq * 16, sh);
            cp16(base + 10240 + m * IPROW + kq * 16, sl);
            const __nv_bfloat16* bh = winH + (size_t)(n0 + m) * PE + kt0 + kq * 8;
            const __nv_bfloat16* bl = winL + (size_t)(n0 + m) * PE + kt0 + kq * 8;
            cp16(base + 20480 + m * IPROW + kq * 16, bh);
            cp16(base + 30720 + m * IPROW + kq * 16, bl);
        }
    };

    stage(0, 0); cp_commit();
#pragma unroll 1
    for (int c = 0; c < 8; c++) {
        cp_wait0();
        __syncthreads();
        if (c < 7) { stage((c + 1) & 1, c + 1); cp_commit(); }
        uint32_t base = smb + (c & 1) * IP_BUF;
#pragma unroll
        for (int kt = 0; kt < 2; kt++) {
            uint32_t bh[4][2], bl[4][2];
#pragma unroll
            for (int nt = 0; nt < 4; nt++) {
                uint32_t a = base + 20480 +
                    (uint32_t)((wn * 32 + nt * 8 + (lane >> 2)) * IPROW + kt * 32 + (lane & 3) * 4);
                asm volatile("ld.shared.b32 %0, [%1];" : "=r"(bh[nt][0]) : "r"(a));
                asm volatile("ld.shared.b32 %0, [%1];" : "=r"(bh[nt][1]) : "r"(a + 16));
                asm volatile("ld.shared.b32 %0, [%1];" : "=r"(bl[nt][0]) : "r"(a + 10240));
                asm volatile("ld.shared.b32 %0, [%1];" : "=r"(bl[nt][1]) : "r"(a + 10240 + 16));
            }
            uint32_t ah[4][4], al[4][4];
#pragma unroll
            for (int mt = 0; mt < 4; mt++) {
                uint32_t a = base +
                    (uint32_t)((wm * 64 + mt * 16 + (lane & 15)) * IPROW + (lane >> 4) * 16 + kt * 32);
                ldsm_x4(ah[mt], a);
                ldsm_x4(al[mt], a + 10240);
            }
#pragma unroll
            for (int mt = 0; mt < 4; mt++)
#pragma unroll
                for (int nt = 0; nt < 4; nt++) mma_bf16(acc[mt][nt], ah[mt], bh[nt]);
#pragma unroll
            for (int mt = 0; mt < 4; mt++)
#pragma unroll
                for (int nt = 0; nt < 4; nt++) mma_bf16(acc[mt][nt], ah[mt], bl[nt]);
#pragma unroll
            for (int mt = 0; mt < 4; mt++)
#pragma unroll
                for (int nt = 0; nt < 4; nt++) mma_bf16(acc[mt][nt], al[mt], bh[nt]);
        }
    }

#pragma unroll
    for (int mt = 0; mt < 4; mt++) {
        int mg = m0 + wm * 64 + mt * 16 + (lane >> 2);
#pragma unroll
        for (int nt = 0; nt < 4; nt++) {
            int ng = n0 + wn * 32 + nt * 8 + (lane & 3) * 2;
            *(float2*)(xp + (size_t)mg * PC3 + ng) =
                make_float2(acc[mt][nt][0] + bv[nt].x, acc[mt][nt][1] + bv[nt].y);
            *(float2*)(xp + (size_t)(mg + 8) * PC3 + ng) =
                make_float2(acc[mt][nt][2] + bv[nt].x, acc[mt][nt][3] + bv[nt].y);
        }
    }
}

// ---------------------------------------------------------------------------
// stage one 256-k chunk of A = [h_hi(64); h_lo(64)], LDG batched 8-deep
// ---------------------------------------------------------------------------
__device__ __forceinline__ void stage_chunk(char* Abuf,
                                            const __nv_bfloat16* __restrict__ sHi,
                                            const __nv_bfloat16* __restrict__ sLo,
                                            int kc, int tid)
{
#pragma unroll
    for (int h = 0; h < 2; h++) {
        uint4 v[8];
#pragma unroll
        for (int i = 0; i < 8; i++) {
            int fl = tid + (h * 8 + i) * TPB;
            int m  = fl >> 5;
            int kq = fl & 31;
            const __nv_bfloat16* p = (m < 64)
                ? (sHi + (size_t)m * PU + kc + kq * 8)
                : (sLo + (size_t)(m - 64) * PU + kc + kq * 8);
            v[i] = *(const uint4*)p;
        }
#pragma unroll
        for (int i = 0; i < 8; i++) {
            int fl = tid + (h * 8 + i) * TPB;
            int m  = fl >> 5;
            int kq = fl & 31;
            *(uint4*)(Abuf + m * AROWB + kq * 16) = v[i];
        }
    }
}

// ---------------------------------------------------------------------------
// Kernel 2: persistent GRU scan (R7-proven staging; split arrive/wait barrier)
// ---------------------------------------------------------------------------
__global__ __launch_bounds__(TPB, 1) void k_gru(
    const float* __restrict__ xp,
    const float* __restrict__ h0,
    const float* __restrict__ Wrec,
    const float* __restrict__ brec,
    float* __restrict__ out,
    float* __restrict__ hlast)
{
    extern __shared__ char sm[];
    const uint32_t smb = smem_u32(sm);
    const int tid   = threadIdx.x;
    const int warp  = tid >> 5;
    const int lane  = tid & 31;
    const int ubase = blockIdx.x * TILE_U;

    __nv_bfloat16* WloS = (__nv_bfloat16*)(sm + SM_WLO);
    float* os  = (float*)(sm + SM_OS);
    uint32_t* osh = (uint32_t*)(sm + SM_OSH);
    uint32_t* osl = (uint32_t*)(sm + SM_OSL);
    float* brs = (float*)(sm + SM_BRS);
    float* Dp  = (float*)sm;

    // Whi register fragments: warp's 8 ktiles = c*16 + warp*2 + j
    uint32_t Bh[8][3][2];
#pragma unroll
    for (int c = 0; c < 4; c++)
#pragma unroll
        for (int j = 0; j < 2; j++) {
            int KT = c * 16 + warp * 2 + j;
            int k0 = KT * 16 + (lane & 3) * 2;
#pragma unroll
            for (int nt = 0; nt < 3; nt++) {
                int n = nt * 8 + (lane >> 2);
                int col = (n >> 3) * PU + ubase + (n & 7);
                float w0 = Wrec[(size_t)k0 * PC3 + col];
                float w1 = Wrec[(size_t)(k0 + 1) * PC3 + col];
                float w8 = Wrec[(size_t)(k0 + 8) * PC3 + col];
                float w9 = Wrec[(size_t)(k0 + 9) * PC3 + col];
                Bh[c * 2 + j][nt][0] = pack_bf16x2(__bfloat162float(__float2bfloat16_rn(w0)),
                                                   __bfloat162float(__float2bfloat16_rn(w1)));
                Bh[c * 2 + j][nt][1] = pack_bf16x2(__bfloat162float(__float2bfloat16_rn(w8)),
                                                   __bfloat162float(__float2bfloat16_rn(w9)));
            }
        }
    for (int idx = tid; idx < NCOL * PU; idx += TPB) {
        int n = idx >> 10, k = idx & 1023;
        int col = (n >> 3) * PU + ubase + (n & 7);
        float w = Wrec[(size_t)k * PC3 + col];
        float whi = __bfloat162float(__float2bfloat16_rn(w));
        WloS[n * WLOST + k] = __float2bfloat16_rn(w - whi);
    }
    if (tid < NCOL) brs[tid] = brec[(tid >> 3) * PU + ubase + (tid & 7)];
    __syncthreads();

    const int eb = tid >> 2;         // epilogue batch 0..63
    const int uo = tid & 3;          // u-pair 0..3
    const uint32_t laneoff = (uint32_t)((lane & 15) * AROWB + (lane >> 4) * 16);

    // prologue prefetch for t=0
    float2 xz, xr, xh, hp;
    {
        const float* xrow = xp + (size_t)eb * PC3 + ubase + uo * 2;
        xz = *(const float2*)(xrow);
        xr = *(const float2*)(xrow + PU);
        xh = *(const float2*)(xrow + 2 * PU);
        hp = *(const float2*)(h0 + (size_t)eb * PU + ubase + uo * 2);
    }

    for (int t = 0; t < PT; t++) {
        const int par = t & 1;
        const __nv_bfloat16* sHi = g_hhi[par];
        const __nv_bfloat16* sLo = g_hlo[par];
        __nv_bfloat16* dHi = g_hhi[par ^ 1];
        __nv_bfloat16* dLo = g_hlo[par ^ 1];

        float acc[8][3][4];
#pragma unroll
        for (int mt = 0; mt < 8; mt++)
#pragma unroll
            for (int nt = 0; nt < 3; nt++)
#pragma unroll
                for (int r = 0; r < 4; r++) acc[mt][nt][r] = 0.f;

        stage_chunk(sm, sHi, sLo, 0, tid);
        __syncthreads();

#pragma unroll 1
        for (int c = 0; c < NCHNK; c++) {
            const uint32_t abase = smb + (uint32_t)((c & 1) * ABUFB);
#pragma unroll
            for (int j = 0; j < 2; j++) {
                const int ktl = warp * 2 + j;
                const int KT  = c * 16 + ktl;
                uint32_t bl[3][2];
#pragma unroll
                for (int nt = 0; nt < 3; nt++) {
                    int n = nt * 8 + (lane >> 2);
                    const __nv_bfloat16* wl = WloS + n * WLOST + KT * 16 + (lane & 3) * 2;
                    bl[nt][0] = *(const uint32_t*)(wl);
                    bl[nt][1] = *(const uint32_t*)(wl + 8);
                }
#pragma unroll
                for (int mt = 0; mt < 8; mt++) {
                    uint32_t a[4];
                    ldsm_x4(a, abase + (uint32_t)(mt * 16 * AROWB + ktl * 32) + laneoff);
#pragma unroll
                    for (int nt = 0; nt < 3; nt++) mma_bf16(acc[mt][nt], a, Bh[c * 2 + j][nt]);
                    if (mt < 4) {
#pragma unroll
                        for (int nt = 0; nt < 3; nt++) mma_bf16(acc[mt][nt], a, bl[nt]);
                    }
                }
            }
            if (c < NCHNK - 1)
                stage_chunk(sm + ((c + 1) & 1) * ABUFB, sHi, sLo, (c + 1) * KCHUNK, tid);
            __syncthreads();
        }

        // ---- k-partials to smem (overlay A; all MMA reads done) ----
#pragma unroll
        for (int mt = 0; mt < 8; mt++)
#pragma unroll
            for (int nt = 0; nt < 3; nt++) {
                int m = mt * 16 + (lane >> 2);
                int n = nt * 8 + (lane & 3) * 2;
                *(float2*)&Dp[((warp << 7) + m) * DPST + n] =
                    make_float2(acc[mt][nt][0], acc[mt][nt][1]);
                *(float2*)&Dp[((warp << 7) + m + 8) * DPST + n] =
                    make_float2(acc[mt][nt][2], acc[mt][nt][3]);
            }
        __syncthreads();

        // ---- reduce + gates ----
        {
            float s0 = 0.f, s1 = 0.f, s2 = 0.f, s3 = 0.f, s4 = 0.f, s5 = 0.f;
#pragma unroll
            for (int w = 0; w < 8; w++) {
#pragma unroll
                for (int rr = 0; rr < 2; rr++) {
                    const float* base = Dp + ((w << 7) + eb + rr * 64) * DPST + uo * 2;
                    float2 vz = *(const float2*)(base);
                    float2 vr = *(const float2*)(base + 8);
                    float2 vh = *(const float2*)(base + 16);
                    s0 += vz.x; s1 += vz.y;
                    s2 += vr.x; s3 += vr.y;
                    s4 += vh.x; s5 += vh.y;
                }
            }
            int u0 = uo * 2;
            float z0 = sig_fast(xz.x + s0 + brs[u0]);
            float r0 = sig_fast(xr.x + s2 + brs[8 + u0]);
            float c0 = tanh_fast(xh.x + r0 * (s4 + brs[16 + u0]));
            float hn0 = z0 * hp.x + (1.f - z0) * c0;
            float z1 = sig_fast(xz.y + s1 + brs[u0 + 1]);
            float r1 = sig_fast(xr.y + s3 + brs[8 + u0 + 1]);
            float c1 = tanh_fast(xh.y + r1 * (s5 + brs[16 + u0 + 1]));
            float hn1 = z1 * hp.y + (1.f - z1) * c1;

            *(float2*)&os[eb * 8 + u0] = make_float2(hn0, hn1);
            __nv_bfloat16 h0b = __float2bfloat16_rn(hn0);
            __nv_bfloat16 h1b = __float2bfloat16_rn(hn1);
            osh[eb * 4 + uo] = pack_bf16x2(__bfloat162float(h0b), __bfloat162float(h1b));
            osl[eb * 4 + uo] = pack_bf16x2(hn0 - __bfloat162float(h0b),
                                           hn1 - __bfloat162float(h1b));
        }
        __syncthreads();

        // ---- publish next-step h splits (cross-block critical path) ----
        if (tid < 128) {
            int bb = tid >> 1, hf = tid & 1;
            uint2 vh = *(const uint2*)&osh[bb * 4 + hf * 2];
            uint2 vl = *(const uint2*)&osl[bb * 4 + hf * 2];
            *(uint2*)(dHi + (size_t)bb * PU + ubase + hf * 4) = vh;
            *(uint2*)(dLo + (size_t)bb * PU + ubase + hf * 4) = vl;
        }

        // ---- barrier ARRIVE ----
        __syncthreads();
        unsigned snap = 0;
        if (tid == 0) {
            __threadfence();
            snap = *((volatile unsigned*)&g_bar_gen);
            unsigned prev = atomicAdd(&g_bar_count, 1u);
            if (prev == NBLK - 1u) {
                atomicExch(&g_bar_count, 0u);
                __threadfence();
                atomicAdd(&g_bar_gen, 1u);
            }
        }

        // ---- overlapped with barrier wait: out store + next-step prefetch ----
        if (tid < 128) {
            int bb = tid >> 1, hf = tid & 1;
            float4 v = *(const float4*)&os[bb * 8 + hf * 4];
            *(float4*)(out + ((size_t)bb * PT + t) * PU + ubase + hf * 4) = v;
            if (t == PT - 1 && hlast != nullptr)
                *(float4*)(hlast + (size_t)bb * PU + ubase + hf * 4) = v;
        }
        if (t < PT - 1) {
            const float* xrow = xp + ((size_t)(t + 1) * PB + eb) * PC3 + ubase + uo * 2;
            xz = *(const float2*)(xrow);
            xr = *(const float2*)(xrow + PU);
            xh = *(const float2*)(xrow + 2 * PU);
            hp = *(const float2*)&os[eb * 8 + uo * 2];
        }

        // ---- barrier WAIT ----
        if (tid == 0) {
            while (*((volatile unsigned*)&g_bar_gen) == snap) { }
            __threadfence();
        }
        __syncthreads();
    }
}

// ---------------------------------------------------------------------------
// launch
// ---------------------------------------------------------------------------
extern "C" void kernel_launch(void* const* d_in, const int* in_sizes, int n_in,
                              void* d_out, int out_size)
{
    const int*   x       = (const int*)  d_in[0];
    const float* initial = (const float*)d_in[1];
    const float* emb     = (const float*)d_in[2];
    const float* Win     = (const float*)d_in[3];
    const float* Wrec    = (const float*)d_in[4];
    const float* bin     = (const float*)d_in[5];
    const float* brec    = (const float*)d_in[6];

    float* out = (float*)d_out;
    float* hlast = nullptr;
    const long long n_outputs = (long long)PB * PT * PU;
    if ((long long)out_size >= n_outputs + (long long)PB * PU) {
        hlast = out + (size_t)n_outputs;
    }

    float* xp = nullptr;
    cudaGetSymbolAddress((void**)&xp, g_xp);
    __nv_bfloat16 *hhi, *hlo, *embh, *embl, *winth, *wintl;
    cudaGetSymbolAddress((void**)&hhi, g_hhi);
    cudaGetSymbolAddress((void**)&hlo, g_hlo);
    cudaGetSymbolAddress((void**)&embh, g_embh);
    cudaGetSymbolAddress((void**)&embl, g_embl);
    cudaGetSymbolAddress((void**)&winth, g_winth);
    cudaGetSymbolAddress((void**)&wintl, g_wintl);

    // prep: splits + transpose
    k_split_init<<<(PB * PU + 255) / 256, 256>>>(initial, hhi, hlo);
    k_prep_emb<<<(int)(((size_t)PV * PE / 4 + 255) / 256), 256>>>(emb, embh, embl);
    k_prep_winT<<<(PE * PC3 + 255) / 256, 256>>>(Win, winth, wintl);

    // GEMM1 on tensor cores
    cudaFuncSetAttribute(k_inproj_mma, cudaFuncAttributeMaxDynamicSharedMemorySize, IP_TOTAL);
    dim3 g1(PC3 / 128, (PT * PB) / 128);
    k_inproj_mma<<<g1, 256, IP_TOTAL>>>(x, embh, embl, winth, wintl, bin, xp);

    // persistent GRU scan
    cudaFuncSetAttribute(k_gru, cudaFuncAttributeMaxDynamicSharedMemorySize, SM_TOTAL);
    k_gru<<<NBLK, TPB, SM_TOTAL>>>(xp, initial, Wrec, brec, out, hlast);
}